// round 1
// baseline (speedup 1.0000x reference)
#include <cuda_runtime.h>
#include <cuda_bf16.h>

// Problem constants
#define BB 8
#define TT 2048
#define HH 1024
#define MM (BB*TT)        // 16384
#define NHOP 12
#define THRESH 0.9f
#define LNEPS 1e-5f

// -------- device scratch (no runtime allocation allowed) --------
__device__ float g_c[NHOP * HH];      // c_k[o] = pos_k @ Wt^T + bt
__device__ float g_spk[NHOP];         // pos_k . (gamma*w_p)
__device__ float g_mupos[NHOP];       // mean(pos_k)
__device__ float g_qpos[NHOP];        // mean(pos_k^2)
__device__ float g_C0;                // beta.w_p + b_p
__device__ float g_G;                 // sum(gamma*w_p)
__device__ float g_Acoef[MM];         // per-token final scale of baseT
__device__ float g_w[MM * NHOP];      // per-token per-hop weights

__device__ __forceinline__ float warpReduce(float v) {
    #pragma unroll
    for (int o = 16; o > 0; o >>= 1) v += __shfl_xor_sync(0xffffffffu, v, o);
    return v;
}

__device__ __forceinline__ float dot4(float4 a, float4 b) {
    return a.x*b.x + a.y*b.y + a.z*b.z + a.w*b.w;
}

// -------- kernel 0a: per-hop scalar constants --------
__global__ void const_kernel(const float* __restrict__ pos,
                             const float* __restrict__ gamma,
                             const float* __restrict__ beta,
                             const float* __restrict__ wp,
                             const float* __restrict__ bp) {
    const int bid = blockIdx.x;
    const int tid = threadIdx.x;
    __shared__ float red[3][8];
    const int lane = tid & 31, wid = tid >> 5;
    if (bid < NHOP) {
        float sp = 0.f, mp = 0.f, qp = 0.f;
        for (int h = tid; h < HH; h += 256) {
            float pv = pos[bid*HH + h];
            sp += pv * gamma[h] * wp[h];
            mp += pv;
            qp += pv * pv;
        }
        sp = warpReduce(sp); mp = warpReduce(mp); qp = warpReduce(qp);
        if (lane == 0) { red[0][wid] = sp; red[1][wid] = mp; red[2][wid] = qp; }
        __syncthreads();
        if (tid == 0) {
            float s = 0.f, m = 0.f, q = 0.f;
            #pragma unroll
            for (int i = 0; i < 8; i++) { s += red[0][i]; m += red[1][i]; q += red[2][i]; }
            g_spk[bid] = s;
            g_mupos[bid] = m * (1.f / HH);
            g_qpos[bid] = q * (1.f / HH);
        }
    } else {
        float c0 = 0.f, g = 0.f;
        for (int h = tid; h < HH; h += 256) {
            c0 += beta[h] * wp[h];
            g  += gamma[h] * wp[h];
        }
        c0 = warpReduce(c0); g = warpReduce(g);
        if (lane == 0) { red[0][wid] = c0; red[1][wid] = g; }
        __syncthreads();
        if (tid == 0) {
            float s = 0.f, s2 = 0.f;
            #pragma unroll
            for (int i = 0; i < 8; i++) { s += red[0][i]; s2 += red[1][i]; }
            g_C0 = s + bp[0];
            g_G = s2;
        }
    }
}

// -------- kernel 0b: c_k[o] = sum_h pos[k,h]*Wt[o,h] + bt[o] --------
__global__ void ck_kernel(const float* __restrict__ pos,
                          const float* __restrict__ Wt,
                          const float* __restrict__ bt) {
    const int o = blockIdx.x;
    const int tid = threadIdx.x;   // 128 threads
    float acc[NHOP];
    #pragma unroll
    for (int k = 0; k < NHOP; k++) acc[k] = 0.f;
    for (int h = tid; h < HH; h += 128) {
        float w = Wt[o*HH + h];
        #pragma unroll
        for (int k = 0; k < NHOP; k++) acc[k] += w * pos[k*HH + h];
    }
    __shared__ float red[NHOP][4];
    const int lane = tid & 31, wid = tid >> 5;
    #pragma unroll
    for (int k = 0; k < NHOP; k++) {
        float r = warpReduce(acc[k]);
        if (lane == 0) red[k][wid] = r;
    }
    __syncthreads();
    if (tid < NHOP) {
        float s = red[tid][0] + red[tid][1] + red[tid][2] + red[tid][3];
        g_c[tid*HH + o] = s + bt[o];
    }
}

// -------- kernel 1: per-token stats + ACT scalar recurrence --------
__global__ __launch_bounds__(256)
void token_stats_kernel(const float* __restrict__ inp,
                        const float* __restrict__ tenc,
                        const float* __restrict__ pos,
                        const float* __restrict__ gamma,
                        const float* __restrict__ wp,
                        float* __restrict__ out_rem,
                        float* __restrict__ out_nup) {
    const int m = blockIdx.x;
    const int tid = threadIdx.x;

    const float4* in4 = (const float4*)inp + (size_t)m * (HH/4);
    const float4* t4p = (const float4*)tenc + (size_t)(m & (TT-1)) * (HH/4);
    float4 a = in4[tid], t = t4p[tid];
    float4 b4 = make_float4(a.x + t.x, a.y + t.y, a.z + t.z, a.w + t.w);

    float4 ga = ((const float4*)gamma)[tid];
    float4 w4 = ((const float4*)wp)[tid];
    float4 g4 = make_float4(ga.x*w4.x, ga.y*w4.y, ga.z*w4.z, ga.w*w4.w);

    float vals[15];
    vals[0] = b4.x + b4.y + b4.z + b4.w;   // sum(base)
    vals[1] = dot4(b4, b4);                // sum(base^2)
    vals[2] = dot4(b4, g4);                // base . (gamma*wp)
    const float4* p4 = (const float4*)pos;
    #pragma unroll
    for (int k = 0; k < NHOP; k++) {
        float4 pv = p4[k*(HH/4) + tid];
        vals[3+k] = dot4(b4, pv);
    }

    __shared__ float red[15][8];
    const int lane = tid & 31, wid = tid >> 5;
    #pragma unroll
    for (int v = 0; v < 15; v++) {
        float r = warpReduce(vals[v]);
        if (lane == 0) red[v][wid] = r;
    }
    __syncthreads();

    if (tid == 0) {
        float tot[15];
        #pragma unroll
        for (int v = 0; v < 15; v++) {
            float s = 0.f;
            #pragma unroll
            for (int i = 0; i < 8; i++) s += red[v][i];
            tot[v] = s;
        }
        const float mu_b = tot[0] * (1.f / HH);
        const float q_b  = tot[1] * (1.f / HH);
        const float S_b  = tot[2];
        const float G = g_G, C0 = g_C0;

        float hp = 0.f, rem = 0.f, nup = 0.f;
        float uw[NHOP];
        #pragma unroll
        for (int k = 0; k < NHOP; k++) {
            float mu  = mu_b + g_mupos[k];
            float ex2 = q_b + 2.f * tot[3+k] * (1.f / HH) + g_qpos[k];
            float var = ex2 - mu * mu;
            float Sg  = S_b + g_spk[k];
            float logit = rsqrtf(var + LNEPS) * (Sg - mu * G) + C0;
            float p = 1.f / (1.f + expf(-logit));

            float sr  = (hp < 1.f) ? 1.f : 0.f;
            float acc = hp + p * sr;
            float nh  = (acc > THRESH) ? sr : 0.f;
            sr        = (acc <= THRESH) ? sr : 0.f;
            hp  = hp + p * sr;
            rem = rem + nh * (1.f - hp);
            hp  = hp + nh * rem;
            nup = nup + sr + nh;
            uw[k] = p * sr + nh * rem;
        }
        // suffix products: w_k = uw_k * prod_{j>k}(1-uw_j)
        float prod = 1.f, A = 0.f;
        #pragma unroll
        for (int k = NHOP-1; k >= 0; k--) {
            float wk = uw[k] * prod;
            g_w[(size_t)m*NHOP + k] = wk;
            A += wk;
            prod *= (1.f - uw[k]);
        }
        g_Acoef[m] = A;
        out_rem[m] = rem;
        out_nup[m] = nup;
    }
}

// -------- kernel 2: SGEMM baseT = (inputs+time_enc) @ Wt^T, fused epilogue --------
// out[m,n] = A[m] * baseT[m,n] + sum_k w[m,k] * c_k[n]
#define GBM 128
#define GBN 128
#define GBK 16

__global__ __launch_bounds__(256)
void gemm_epilogue_kernel(const float* __restrict__ inp,
                          const float* __restrict__ tenc,
                          const float* __restrict__ Wt,
                          float* __restrict__ outp) {
    __shared__ float As[GBK][GBM + 4];
    __shared__ float Bs[GBK][GBN + 4];

    const int tid = threadIdx.x;
    const int bm = blockIdx.y * GBM;
    const int bn = blockIdx.x * GBN;
    const int tx = tid & 15, ty = tid >> 4;

    float acc[8][8];
    #pragma unroll
    for (int i = 0; i < 8; i++)
        #pragma unroll
        for (int j = 0; j < 8; j++) acc[i][j] = 0.f;

    for (int kt = 0; kt < HH; kt += GBK) {
        #pragma unroll
        for (int r = 0; r < 2; r++) {
            int idx = tid + r * 256;          // [0,512)
            int row = idx >> 2;
            int kq  = (idx & 3) * 4;
            {
                int mrow = bm + row;
                const float* pa = inp  + (size_t)mrow * HH + kt + kq;
                const float* pt = tenc + (size_t)(mrow & (TT-1)) * HH + kt + kq;
                float4 av = *(const float4*)pa;
                float4 tv = *(const float4*)pt;
                As[kq+0][row] = av.x + tv.x;
                As[kq+1][row] = av.y + tv.y;
                As[kq+2][row] = av.z + tv.z;
                As[kq+3][row] = av.w + tv.w;
            }
            {
                int nrow = bn + row;
                float4 bv = *(const float4*)(Wt + (size_t)nrow * HH + kt + kq);
                Bs[kq+0][row] = bv.x;
                Bs[kq+1][row] = bv.y;
                Bs[kq+2][row] = bv.z;
                Bs[kq+3][row] = bv.w;
            }
        }
        __syncthreads();
        #pragma unroll
        for (int kk = 0; kk < GBK; kk++) {
            float af[8], bf[8];
            *(float4*)(af)     = *(const float4*)&As[kk][ty*8];
            *(float4*)(af + 4) = *(const float4*)&As[kk][ty*8 + 4];
            *(float4*)(bf)     = *(const float4*)&Bs[kk][tx*8];
            *(float4*)(bf + 4) = *(const float4*)&Bs[kk][tx*8 + 4];
            #pragma unroll
            for (int i = 0; i < 8; i++)
                #pragma unroll
                for (int j = 0; j < 8; j++)
                    acc[i][j] += af[i] * bf[j];
        }
        __syncthreads();
    }

    // epilogue
    const int mrow = bm + ty * 8;
    const int ncol = bn + tx * 8;
    {
        float Ac[8];
        #pragma unroll
        for (int i = 0; i < 8; i++) Ac[i] = g_Acoef[mrow + i];
        #pragma unroll
        for (int i = 0; i < 8; i++)
            #pragma unroll
            for (int j = 0; j < 8; j++) acc[i][j] *= Ac[i];
    }
    #pragma unroll
    for (int k = 0; k < NHOP; k++) {
        float ck[8], wk[8];
        #pragma unroll
        for (int j = 0; j < 8; j++) ck[j] = g_c[k*HH + ncol + j];
        #pragma unroll
        for (int i = 0; i < 8; i++) wk[i] = g_w[(size_t)(mrow + i)*NHOP + k];
        #pragma unroll
        for (int i = 0; i < 8; i++)
            #pragma unroll
            for (int j = 0; j < 8; j++)
                acc[i][j] += wk[i] * ck[j];
    }
    #pragma unroll
    for (int i = 0; i < 8; i++) {
        float* po = outp + (size_t)(mrow + i) * HH + ncol;
        *(float4*)(po)     = make_float4(acc[i][0], acc[i][1], acc[i][2], acc[i][3]);
        *(float4*)(po + 4) = make_float4(acc[i][4], acc[i][5], acc[i][6], acc[i][7]);
    }
}

extern "C" void kernel_launch(void* const* d_in, const int* in_sizes, int n_in,
                              void* d_out, int out_size) {
    const float* inp   = (const float*)d_in[0];
    const float* tenc  = (const float*)d_in[1];
    const float* pos   = (const float*)d_in[2];
    const float* gamma = (const float*)d_in[3];
    const float* beta  = (const float*)d_in[4];
    const float* wp    = (const float*)d_in[5];
    const float* bp    = (const float*)d_in[6];
    const float* Wt    = (const float*)d_in[7];
    const float* bt    = (const float*)d_in[8];

    float* outp    = (float*)d_out;
    float* out_rem = outp + (size_t)MM * HH;
    float* out_nup = out_rem + MM;

    const_kernel<<<NHOP + 1, 256>>>(pos, gamma, beta, wp, bp);
    ck_kernel<<<HH, 128>>>(pos, Wt, bt);
    token_stats_kernel<<<MM, 256>>>(inp, tenc, pos, gamma, wp, out_rem, out_nup);
    gemm_epilogue_kernel<<<dim3(HH / GBN, MM / GBM), 256>>>(inp, tenc, Wt, outp);
}

// round 3
// speedup vs baseline: 1.8578x; 1.8578x over previous
#include <cuda_runtime.h>
#include <cuda_bf16.h>
#include <cstdint>
#include <cstddef>

// Problem constants
#define BB 8
#define TT 2048
#define HH 1024
#define MM (BB*TT)        // 16384
#define NHOP 12
#define THRESH 0.9f
#define LNEPS 1e-5f

// Extended-K bf16 GEMM: 3*1024 split + 64 ext (36 used for rank-12 epilogue, 28 zero)
#define KSPL 3072
#define KEXT 64
#define K2   (KSPL + KEXT)   // 3136
#define KT   64              // bf16 per k-tile
#define NT   (K2 / KT)       // 49

// -------- device scratch (static, no runtime allocation) --------
__device__ __nv_bfloat16 g_Asplit[(size_t)MM * K2];   // ~103 MB
__device__ __nv_bfloat16 g_Bsplit[(size_t)HH * K2];   // ~6.4 MB
__device__ float g_c[NHOP * HH];                      // c_k[o] = pos_k @ Wt^T + bt
__device__ float g_spk[NHOP];
__device__ float g_mupos[NHOP];
__device__ float g_qpos[NHOP];
__device__ float g_C0;
__device__ float g_G;

// ======================= helpers =======================
__device__ __forceinline__ uint32_t smem_u32(const void* p) {
    uint32_t a;
    asm("{ .reg .u64 t; cvta.to.shared.u64 t, %1; cvt.u32.u64 %0, t; }" : "=r"(a) : "l"(p));
    return a;
}

__device__ __forceinline__ void cp16(uint32_t dst, const void* src) {
    asm volatile("cp.async.cg.shared.global [%0], [%1], 16;" :: "r"(dst), "l"(src));
}
#define CP_COMMIT() asm volatile("cp.async.commit_group;" ::: "memory")

#define LDSM4(R, addr) \
    asm volatile("ldmatrix.sync.aligned.m8n8.x4.shared.b16 {%0,%1,%2,%3}, [%4];" \
        : "=r"((R)[0]), "=r"((R)[1]), "=r"((R)[2]), "=r"((R)[3]) : "r"(addr))

#define MMA16816(C, A, b0, b1) \
    asm volatile("mma.sync.aligned.m16n8k16.row.col.f32.bf16.bf16.f32 " \
        "{%0,%1,%2,%3}, {%4,%5,%6,%7}, {%8,%9}, {%0,%1,%2,%3};" \
        : "+f"((C)[0]), "+f"((C)[1]), "+f"((C)[2]), "+f"((C)[3]) \
        : "r"((A)[0]), "r"((A)[1]), "r"((A)[2]), "r"((A)[3]), "r"(b0), "r"(b1))

__device__ __forceinline__ float warpReduce(float v) {
    #pragma unroll
    for (int o = 16; o > 0; o >>= 1) v += __shfl_xor_sync(0xffffffffu, v, o);
    return v;
}
__device__ __forceinline__ float dot4(float4 a, float4 b) {
    return a.x*b.x + a.y*b.y + a.z*b.z + a.w*b.w;
}

// split v into bf16 hi/lo
__device__ __forceinline__ void bsplit(float v, __nv_bfloat16& hi, __nv_bfloat16& lo) {
    hi = __float2bfloat16_rn(v);
    lo = __float2bfloat16_rn(v - __bfloat162float(hi));
}

// ======================= kernel 0a: per-hop scalar constants =======================
__global__ void const_kernel(const float* __restrict__ pos,
                             const float* __restrict__ gamma,
                             const float* __restrict__ beta,
                             const float* __restrict__ wp,
                             const float* __restrict__ bp) {
    const int bid = blockIdx.x;
    const int tid = threadIdx.x;
    __shared__ float red[3][8];
    const int lane = tid & 31, wid = tid >> 5;
    if (bid < NHOP) {
        float sp = 0.f, mp = 0.f, qp = 0.f;
        for (int h = tid; h < HH; h += 256) {
            float pv = pos[bid*HH + h];
            sp += pv * gamma[h] * wp[h];
            mp += pv;
            qp += pv * pv;
        }
        sp = warpReduce(sp); mp = warpReduce(mp); qp = warpReduce(qp);
        if (lane == 0) { red[0][wid] = sp; red[1][wid] = mp; red[2][wid] = qp; }
        __syncthreads();
        if (tid == 0) {
            float s = 0.f, m = 0.f, q = 0.f;
            #pragma unroll
            for (int i = 0; i < 8; i++) { s += red[0][i]; m += red[1][i]; q += red[2][i]; }
            g_spk[bid] = s;
            g_mupos[bid] = m * (1.f / HH);
            g_qpos[bid] = q * (1.f / HH);
        }
    } else {
        float c0 = 0.f, g = 0.f;
        for (int h = tid; h < HH; h += 256) {
            c0 += beta[h] * wp[h];
            g  += gamma[h] * wp[h];
        }
        c0 = warpReduce(c0); g = warpReduce(g);
        if (lane == 0) { red[0][wid] = c0; red[1][wid] = g; }
        __syncthreads();
        if (tid == 0) {
            float s = 0.f, s2 = 0.f;
            #pragma unroll
            for (int i = 0; i < 8; i++) { s += red[0][i]; s2 += red[1][i]; }
            g_C0 = s + bp[0];
            g_G = s2;
        }
    }
}

// ======================= kernel 0b: c_k = pos @ Wt^T + bt =======================
__global__ void ck_kernel(const float* __restrict__ pos,
                          const float* __restrict__ Wt,
                          const float* __restrict__ bt) {
    const int o = blockIdx.x;
    const int tid = threadIdx.x;   // 128 threads
    float acc[NHOP];
    #pragma unroll
    for (int k = 0; k < NHOP; k++) acc[k] = 0.f;
    for (int h = tid; h < HH; h += 128) {
        float w = Wt[o*HH + h];
        #pragma unroll
        for (int k = 0; k < NHOP; k++) acc[k] += w * pos[k*HH + h];
    }
    __shared__ float red[NHOP][4];
    const int lane = tid & 31, wid = tid >> 5;
    #pragma unroll
    for (int k = 0; k < NHOP; k++) {
        float r = warpReduce(acc[k]);
        if (lane == 0) red[k][wid] = r;
    }
    __syncthreads();
    if (tid < NHOP) {
        float s = red[tid][0] + red[tid][1] + red[tid][2] + red[tid][3];
        g_c[tid*HH + o] = s + bt[o];
    }
}

// ======================= kernel 0c: build B_ext rows =======================
// B row n: [0:1024)=hi(Wt[n]), [1024:2048)=hi, [2048:3072)=lo,
//          [3072+k]=c_hi, [3084+k]=c_hi, [3096+k]=c_lo, [3108:3136)=0
__global__ __launch_bounds__(256)
void splitB_kernel(const float* __restrict__ Wt) {
    const int o = blockIdx.x;
    const int tid = threadIdx.x;
    __nv_bfloat16* dst = g_Bsplit + (size_t)o * K2;

    float4 v = ((const float4*)(Wt + (size_t)o * HH))[tid];
    __nv_bfloat16 hi[4], lo[4];
    bsplit(v.x, hi[0], lo[0]);
    bsplit(v.y, hi[1], lo[1]);
    bsplit(v.z, hi[2], lo[2]);
    bsplit(v.w, hi[3], lo[3]);
    uint2 hp = *(uint2*)hi;
    uint2 lp = *(uint2*)lo;
    *(uint2*)(dst + 4*tid)          = hp;
    *(uint2*)(dst + HH + 4*tid)     = hp;
    *(uint2*)(dst + 2*HH + 4*tid)   = lp;

    if (tid < KEXT) {
        __nv_bfloat16 val = __float2bfloat16_rn(0.f);
        if (tid < 12) {
            val = __float2bfloat16_rn(g_c[tid*HH + o]);
        } else if (tid < 24) {
            val = __float2bfloat16_rn(g_c[(tid-12)*HH + o]);
        } else if (tid < 36) {
            float c = g_c[(tid-24)*HH + o];
            __nv_bfloat16 h = __float2bfloat16_rn(c);
            val = __float2bfloat16_rn(c - __bfloat162float(h));
        }
        dst[KSPL + tid] = val;
    }
}

// ========= kernel 1: token stats + ACT recurrence + scaled A split (fused) =========
// A row m: [0:1024)=hi(Ac*base), [1024:2048)=lo, [2048:3072)=hi,
//          [3072+k]=w_hi, [3084+k]=w_lo, [3096+k]=w_hi, [3108:3136)=0
__global__ __launch_bounds__(256)
void token_stats_kernel(const float* __restrict__ inp,
                        const float* __restrict__ tenc,
                        const float* __restrict__ pos,
                        const float* __restrict__ gamma,
                        const float* __restrict__ wp,
                        float* __restrict__ out_rem,
                        float* __restrict__ out_nup) {
    const int m = blockIdx.x;
    const int tid = threadIdx.x;

    const float4* in4 = (const float4*)inp + (size_t)m * (HH/4);
    const float4* t4p = (const float4*)tenc + (size_t)(m & (TT-1)) * (HH/4);
    float4 a = in4[tid], t = t4p[tid];
    float4 b4 = make_float4(a.x + t.x, a.y + t.y, a.z + t.z, a.w + t.w);

    float4 ga = ((const float4*)gamma)[tid];
    float4 w4 = ((const float4*)wp)[tid];
    float4 g4 = make_float4(ga.x*w4.x, ga.y*w4.y, ga.z*w4.z, ga.w*w4.w);

    float vals[15];
    vals[0] = b4.x + b4.y + b4.z + b4.w;
    vals[1] = dot4(b4, b4);
    vals[2] = dot4(b4, g4);
    const float4* p4 = (const float4*)pos;
    #pragma unroll
    for (int k = 0; k < NHOP; k++) {
        float4 pv = p4[k*(HH/4) + tid];
        vals[3+k] = dot4(b4, pv);
    }

    __shared__ float red[15][8];
    __shared__ float s_b[13];     // w[0..11], Acoef
    const int lane = tid & 31, wid = tid >> 5;
    #pragma unroll
    for (int v = 0; v < 15; v++) {
        float r = warpReduce(vals[v]);
        if (lane == 0) red[v][wid] = r;
    }
    __syncthreads();

    if (tid == 0) {
        float tot[15];
        #pragma unroll
        for (int v = 0; v < 15; v++) {
            float s = 0.f;
            #pragma unroll
            for (int i = 0; i < 8; i++) s += red[v][i];
            tot[v] = s;
        }
        const float mu_b = tot[0] * (1.f / HH);
        const float q_b  = tot[1] * (1.f / HH);
        const float S_b  = tot[2];
        const float G = g_G, C0 = g_C0;

        float hp = 0.f, rem = 0.f, nup = 0.f;
        float uw[NHOP];
        #pragma unroll
        for (int k = 0; k < NHOP; k++) {
            float mu  = mu_b + g_mupos[k];
            float ex2 = q_b + 2.f * tot[3+k] * (1.f / HH) + g_qpos[k];
            float var = ex2 - mu * mu;
            float Sg  = S_b + g_spk[k];
            float logit = rsqrtf(var + LNEPS) * (Sg - mu * G) + C0;
            float p = 1.f / (1.f + expf(-logit));

            float sr  = (hp < 1.f) ? 1.f : 0.f;
            float acc = hp + p * sr;
            float nh  = (acc > THRESH) ? sr : 0.f;
            sr        = (acc <= THRESH) ? sr : 0.f;
            hp  = hp + p * sr;
            rem = rem + nh * (1.f - hp);
            hp  = hp + nh * rem;
            nup = nup + sr + nh;
            uw[k] = p * sr + nh * rem;
        }
        float prod = 1.f, A = 0.f;
        #pragma unroll
        for (int k = NHOP-1; k >= 0; k--) {
            float wk = uw[k] * prod;
            s_b[k] = wk;
            A += wk;
            prod *= (1.f - uw[k]);
        }
        s_b[12] = A;
        out_rem[m] = rem;
        out_nup[m] = nup;
    }
    __syncthreads();

    const float Ac = s_b[12];
    __nv_bfloat16* dst = g_Asplit + (size_t)m * K2;
    {
        float sx = Ac * b4.x, sy = Ac * b4.y, sz = Ac * b4.z, sw = Ac * b4.w;
        __nv_bfloat16 hi[4], lo[4];
        bsplit(sx, hi[0], lo[0]);
        bsplit(sy, hi[1], lo[1]);
        bsplit(sz, hi[2], lo[2]);
        bsplit(sw, hi[3], lo[3]);
        uint2 hp2 = *(uint2*)hi;
        uint2 lp2 = *(uint2*)lo;
        *(uint2*)(dst + 4*tid)        = hp2;
        *(uint2*)(dst + HH + 4*tid)   = lp2;
        *(uint2*)(dst + 2*HH + 4*tid) = hp2;
    }
    if (tid < KEXT) {
        __nv_bfloat16 val = __float2bfloat16_rn(0.f);
        if (tid < 12) {
            val = __float2bfloat16_rn(s_b[tid]);
        } else if (tid < 24) {
            float w = s_b[tid-12];
            __nv_bfloat16 h = __float2bfloat16_rn(w);
            val = __float2bfloat16_rn(w - __bfloat162float(h));
        } else if (tid < 36) {
            val = __float2bfloat16_rn(s_b[tid-24]);
        }
        dst[KSPL + tid] = val;
    }
}

// ======================= kernel 2: bf16 mma.sync GEMM =======================
// out[m,n] = sum_k A_ext[m,k] * B_ext[n,k]   (256x128 CTA tile, 64x64 warp tile)

#define TM 256
#define TN 128
#define ROWB 144                       // padded row bytes: 72 bf16
#define ABYTES (TM * ROWB)             // 36864
#define BBYTES (TN * ROWB)             // 18432
#define SMEM_GEMM (2*ABYTES + 2*BBYTES) // 110592

__device__ __forceinline__ void load_tiles(uint32_t sa, int buf, int kt, int bm, int bn, int tid) {
    const __nv_bfloat16* Ab = g_Asplit + (size_t)bm * K2 + kt * KT;
    uint32_t adst = sa + buf * ABYTES;
    #pragma unroll
    for (int i = 0; i < 8; i++) {
        int id = tid + i * 256;
        int row = id >> 3, cc = id & 7;
        cp16(adst + row * ROWB + cc * 16, Ab + (size_t)row * K2 + cc * 8);
    }
    const __nv_bfloat16* Bb = g_Bsplit + (size_t)bn * K2 + kt * KT;
    uint32_t bdst = sa + 2 * ABYTES + buf * BBYTES;
    #pragma unroll
    for (int i = 0; i < 4; i++) {
        int id = tid + i * 256;
        int row = id >> 3, cc = id & 7;
        cp16(bdst + row * ROWB + cc * 16, Bb + (size_t)row * K2 + cc * 8);
    }
    CP_COMMIT();
}

__global__ __launch_bounds__(256, 1)
void gemm_mma_kernel(float* __restrict__ outp) {
    extern __shared__ char smem[];
    uint32_t sa = smem_u32(smem);
    const int tid = threadIdx.x;
    const int lane = tid & 31;
    const int warp = tid >> 5;
    const int wm = (warp & 3) * 64;    // 4 warps along M
    const int wn = (warp >> 2) * 64;   // 2 warps along N
    const int bm = blockIdx.y * TM;
    const int bn = blockIdx.x * TN;

    const int g = lane >> 3, r = lane & 7;
    const uint32_t a_lm = sa + (uint32_t)((wm + (g & 1) * 8 + r) * ROWB + (g >> 1) * 16);
    const uint32_t b_lm = sa + 2 * ABYTES + (uint32_t)((wn + (g >> 1) * 8 + r) * ROWB + (g & 1) * 16);

    float acc[4][4][8];
    #pragma unroll
    for (int i = 0; i < 4; i++)
        #pragma unroll
        for (int j = 0; j < 4; j++)
            #pragma unroll
            for (int q = 0; q < 8; q++) acc[i][j][q] = 0.f;

    load_tiles(sa, 0, 0, bm, bn, tid);

    for (int kt = 0; kt < NT; kt++) {
        const int cur = kt & 1;
        if (kt + 1 < NT) {
            load_tiles(sa, cur ^ 1, kt + 1, bm, bn, tid);
            asm volatile("cp.async.wait_group 1;" ::: "memory");
        } else {
            asm volatile("cp.async.wait_group 0;" ::: "memory");
        }
        __syncthreads();

        const uint32_t abuf = a_lm + cur * ABYTES;
        const uint32_t bbuf = b_lm + cur * BBYTES;
        #pragma unroll
        for (int ks = 0; ks < 4; ks++) {
            uint32_t af[4][4];
            #pragma unroll
            for (int mf = 0; mf < 4; mf++)
                LDSM4(af[mf], abuf + mf * (16 * ROWB) + ks * 32);
            uint32_t bf[4][4];
            #pragma unroll
            for (int nf = 0; nf < 4; nf++)
                LDSM4(bf[nf], bbuf + nf * (16 * ROWB) + ks * 32);
            #pragma unroll
            for (int mf = 0; mf < 4; mf++)
                #pragma unroll
                for (int nf = 0; nf < 4; nf++) {
                    MMA16816(acc[mf][nf] + 0, af[mf], bf[nf][0], bf[nf][1]);
                    MMA16816(acc[mf][nf] + 4, af[mf], bf[nf][2], bf[nf][3]);
                }
        }
        __syncthreads();
    }

    // store
    #pragma unroll
    for (int mf = 0; mf < 4; mf++) {
        #pragma unroll
        for (int nf = 0; nf < 4; nf++) {
            const int row0 = bm + wm + mf * 16 + (lane >> 2);
            const int col0 = bn + wn + nf * 16 + (lane & 3) * 2;
            float* p = outp + (size_t)row0 * HH + col0;
            *(float2*)(p)              = make_float2(acc[mf][nf][0], acc[mf][nf][1]);
            *(float2*)(p + 8*HH)       = make_float2(acc[mf][nf][2], acc[mf][nf][3]);
            *(float2*)(p + 8)          = make_float2(acc[mf][nf][4], acc[mf][nf][5]);
            *(float2*)(p + 8*HH + 8)   = make_float2(acc[mf][nf][6], acc[mf][nf][7]);
        }
    }
}

// ======================= host launch =======================
extern "C" void kernel_launch(void* const* d_in, const int* in_sizes, int n_in,
                              void* d_out, int out_size) {
    const float* inp   = (const float*)d_in[0];
    const float* tenc  = (const float*)d_in[1];
    const float* pos   = (const float*)d_in[2];
    const float* gamma = (const float*)d_in[3];
    const float* beta  = (const float*)d_in[4];
    const float* wp    = (const float*)d_in[5];
    const float* bp    = (const float*)d_in[6];
    const float* Wt    = (const float*)d_in[7];
    const float* bt    = (const float*)d_in[8];

    float* outp    = (float*)d_out;
    float* out_rem = outp + (size_t)MM * HH;
    float* out_nup = out_rem + MM;

    cudaFuncSetAttribute(gemm_mma_kernel, cudaFuncAttributeMaxDynamicSharedMemorySize, SMEM_GEMM);

    const_kernel<<<NHOP + 1, 256>>>(pos, gamma, beta, wp, bp);
    ck_kernel<<<HH, 128>>>(pos, Wt, bt);
    splitB_kernel<<<HH, 256>>>(Wt);
    token_stats_kernel<<<MM, 256>>>(inp, tenc, pos, gamma, wp, out_rem, out_nup);
    gemm_mma_kernel<<<dim3(HH / TN, MM / TM), 256, SMEM_GEMM>>>(outp);
}

// round 4
// speedup vs baseline: 2.7183x; 1.4632x over previous
#include <cuda_runtime.h>
#include <cuda_fp16.h>
#include <cstdint>
#include <cstddef>

// Problem constants
#define BB 8
#define TT 2048
#define HH 1024
#define MM (BB*TT)        // 16384
#define NHOP 12
#define THRESH 0.9f
#define LNEPS 1e-5f

// Extended-K fp16 GEMM: [ahi|alo] x [bhi|bhi] + 64 ext cols (36 used for rank-12 epilogue)
#define KSPL 2048
#define KEXT 64
#define K2   (KSPL + KEXT)   // 2112
#define KT   64              // fp16 per k-tile
#define NT   (K2 / KT)       // 33

// -------- device scratch (static, no runtime allocation) --------
__device__ __half g_Asplit[(size_t)MM * K2];   // ~69 MB
__device__ __half g_Bsplit[(size_t)HH * K2];   // ~4.3 MB
__device__ float g_c[NHOP * HH];               // c_k[o] = pos_k @ Wt^T + bt
__device__ float g_gw[HH];                     // gamma*wp
__device__ float g_spk[NHOP];
__device__ float g_mupos[NHOP];
__device__ float g_qpos[NHOP];
__device__ float g_C0;
__device__ float g_G;

// ======================= helpers =======================
__device__ __forceinline__ uint32_t smem_u32(const void* p) {
    uint32_t a;
    asm("{ .reg .u64 t; cvta.to.shared.u64 t, %1; cvt.u32.u64 %0, t; }" : "=r"(a) : "l"(p));
    return a;
}

__device__ __forceinline__ void cp16(uint32_t dst, const void* src) {
    asm volatile("cp.async.cg.shared.global [%0], [%1], 16;" :: "r"(dst), "l"(src));
}
#define CP_COMMIT() asm volatile("cp.async.commit_group;" ::: "memory")

#define LDSM4(R, addr) \
    asm volatile("ldmatrix.sync.aligned.m8n8.x4.shared.b16 {%0,%1,%2,%3}, [%4];" \
        : "=r"((R)[0]), "=r"((R)[1]), "=r"((R)[2]), "=r"((R)[3]) : "r"(addr))

#define MMA16816(C, A, b0, b1) \
    asm volatile("mma.sync.aligned.m16n8k16.row.col.f32.f16.f16.f32 " \
        "{%0,%1,%2,%3}, {%4,%5,%6,%7}, {%8,%9}, {%0,%1,%2,%3};" \
        : "+f"((C)[0]), "+f"((C)[1]), "+f"((C)[2]), "+f"((C)[3]) \
        : "r"((A)[0]), "r"((A)[1]), "r"((A)[2]), "r"((A)[3]), "r"(b0), "r"(b1))

__device__ __forceinline__ float warpReduce(float v) {
    #pragma unroll
    for (int o = 16; o > 0; o >>= 1) v += __shfl_xor_sync(0xffffffffu, v, o);
    return v;
}
__device__ __forceinline__ float dot4(float4 a, float4 b) {
    return a.x*b.x + a.y*b.y + a.z*b.z + a.w*b.w;
}

// split v into fp16 hi/lo
__device__ __forceinline__ void hsplit(float v, __half& hi, __half& lo) {
    hi = __float2half_rn(v);
    lo = __float2half_rn(v - __half2float(hi));
}

// ======================= kernel 0a: per-hop scalar constants + gw =======================
__global__ void const_kernel(const float* __restrict__ pos,
                             const float* __restrict__ gamma,
                             const float* __restrict__ beta,
                             const float* __restrict__ wp,
                             const float* __restrict__ bp) {
    const int bid = blockIdx.x;
    const int tid = threadIdx.x;
    __shared__ float red[3][8];
    const int lane = tid & 31, wid = tid >> 5;
    if (bid < NHOP) {
        float sp = 0.f, mp = 0.f, qp = 0.f;
        for (int h = tid; h < HH; h += 256) {
            float pv = pos[bid*HH + h];
            sp += pv * gamma[h] * wp[h];
            mp += pv;
            qp += pv * pv;
        }
        sp = warpReduce(sp); mp = warpReduce(mp); qp = warpReduce(qp);
        if (lane == 0) { red[0][wid] = sp; red[1][wid] = mp; red[2][wid] = qp; }
        __syncthreads();
        if (tid == 0) {
            float s = 0.f, m = 0.f, q = 0.f;
            #pragma unroll
            for (int i = 0; i < 8; i++) { s += red[0][i]; m += red[1][i]; q += red[2][i]; }
            g_spk[bid] = s;
            g_mupos[bid] = m * (1.f / HH);
            g_qpos[bid] = q * (1.f / HH);
        }
    } else {
        float c0 = 0.f, g = 0.f;
        for (int h = tid; h < HH; h += 256) {
            float gw = gamma[h] * wp[h];
            g_gw[h] = gw;
            c0 += beta[h] * wp[h];
            g  += gw;
        }
        c0 = warpReduce(c0); g = warpReduce(g);
        if (lane == 0) { red[0][wid] = c0; red[1][wid] = g; }
        __syncthreads();
        if (tid == 0) {
            float s = 0.f, s2 = 0.f;
            #pragma unroll
            for (int i = 0; i < 8; i++) { s += red[0][i]; s2 += red[1][i]; }
            g_C0 = s + bp[0];
            g_G = s2;
        }
    }
}

// ======================= kernel 0b: c_k = pos @ Wt^T + bt =======================
__global__ void ck_kernel(const float* __restrict__ pos,
                          const float* __restrict__ Wt,
                          const float* __restrict__ bt) {
    const int o = blockIdx.x;
    const int tid = threadIdx.x;   // 128 threads
    float acc[NHOP];
    #pragma unroll
    for (int k = 0; k < NHOP; k++) acc[k] = 0.f;
    for (int h = tid; h < HH; h += 128) {
        float w = Wt[o*HH + h];
        #pragma unroll
        for (int k = 0; k < NHOP; k++) acc[k] += w * pos[k*HH + h];
    }
    __shared__ float red[NHOP][4];
    const int lane = tid & 31, wid = tid >> 5;
    #pragma unroll
    for (int k = 0; k < NHOP; k++) {
        float r = warpReduce(acc[k]);
        if (lane == 0) red[k][wid] = r;
    }
    __syncthreads();
    if (tid < NHOP) {
        float s = red[tid][0] + red[tid][1] + red[tid][2] + red[tid][3];
        g_c[tid*HH + o] = s + bt[o];
    }
}

// ======================= kernel 0c: build B_ext rows =======================
// B row n: [0:1024)=hi(Wt[n]), [1024:2048)=hi,
//          ext: [0:12)=c_hi, [12:24)=c_hi, [24:36)=c_lo, [36:64)=0
__global__ __launch_bounds__(256)
void splitB_kernel(const float* __restrict__ Wt) {
    const int o = blockIdx.x;
    const int tid = threadIdx.x;
    __half* dst = g_Bsplit + (size_t)o * K2;

    float4 v = ((const float4*)(Wt + (size_t)o * HH))[tid];
    __half hi[4], lo[4];
    hsplit(v.x, hi[0], lo[0]);
    hsplit(v.y, hi[1], lo[1]);
    hsplit(v.z, hi[2], lo[2]);
    hsplit(v.w, hi[3], lo[3]);
    uint2 hp = *(uint2*)hi;
    *(uint2*)(dst + 4*tid)        = hp;
    *(uint2*)(dst + HH + 4*tid)   = hp;

    if (tid < KEXT) {
        __half val = __float2half_rn(0.f);
        if (tid < 24) {
            int k = (tid < 12) ? tid : tid - 12;
            val = __float2half_rn(g_c[k*HH + o]);
        } else if (tid < 36) {
            float c = g_c[(tid-24)*HH + o];
            __half h = __float2half_rn(c);
            val = __float2half_rn(c - __half2float(h));
        }
        dst[KSPL + tid] = val;
    }
}

// ========= kernel 1: warp-per-token stats + ACT + scaled A split (fused) =========
// A row m: [0:1024)=hi(Ac*base), [1024:2048)=lo(Ac*base),
//          ext: [0:12)=w_hi, [12:24)=w_lo, [24:36)=w_hi, [36:64)=0
__global__ __launch_bounds__(256)
void token_stats_kernel(const float* __restrict__ inp,
                        const float* __restrict__ tenc,
                        const float* __restrict__ pos,
                        float* __restrict__ out_rem,
                        float* __restrict__ out_nup) {
    const int warp = threadIdx.x >> 5;
    const int lane = threadIdx.x & 31;
    const int m = blockIdx.x * 8 + warp;

    const float4* in4 = (const float4*)inp + (size_t)m * (HH/4);
    const float4* t4p = (const float4*)tenc + (size_t)(m & (TT-1)) * (HH/4);
    const float4* gw4 = (const float4*)g_gw;
    const float4* p4  = (const float4*)pos;

    float4 bx[8];
    float s0 = 0.f, s1 = 0.f, s2 = 0.f;
    #pragma unroll
    for (int seg = 0; seg < 8; seg++) {
        float4 a = in4[seg*32 + lane];
        float4 t = t4p[seg*32 + lane];
        float4 b = make_float4(a.x+t.x, a.y+t.y, a.z+t.z, a.w+t.w);
        bx[seg] = b;
        s0 += b.x + b.y + b.z + b.w;
        s1 += dot4(b, b);
        s2 += dot4(b, gw4[seg*32 + lane]);
    }
    float sp[NHOP];
    #pragma unroll
    for (int k = 0; k < NHOP; k++) {
        float a = 0.f;
        #pragma unroll
        for (int seg = 0; seg < 8; seg++)
            a += dot4(bx[seg], p4[k*(HH/4) + seg*32 + lane]);
        sp[k] = a;
    }

    // xor-reduce: all lanes end with totals
    s0 = warpReduce(s0); s1 = warpReduce(s1); s2 = warpReduce(s2);
    #pragma unroll
    for (int k = 0; k < NHOP; k++) sp[k] = warpReduce(sp[k]);

    // ACT recurrence (redundant on all lanes)
    const float mu_b = s0 * (1.f / HH);
    const float q_b  = s1 * (1.f / HH);
    const float G = g_G, C0 = g_C0;

    float hp = 0.f, rem = 0.f, nup = 0.f;
    float uw[NHOP];
    #pragma unroll
    for (int k = 0; k < NHOP; k++) {
        float mu  = mu_b + g_mupos[k];
        float ex2 = q_b + 2.f * sp[k] * (1.f / HH) + g_qpos[k];
        float var = ex2 - mu * mu;
        float Sg  = s2 + g_spk[k];
        float logit = rsqrtf(var + LNEPS) * (Sg - mu * G) + C0;
        float p = 1.f / (1.f + expf(-logit));

        float sr  = (hp < 1.f) ? 1.f : 0.f;
        float acc = hp + p * sr;
        float nh  = (acc > THRESH) ? sr : 0.f;
        sr        = (acc <= THRESH) ? sr : 0.f;
        hp  = hp + p * sr;
        rem = rem + nh * (1.f - hp);
        hp  = hp + nh * rem;
        nup = nup + sr + nh;
        uw[k] = p * sr + nh * rem;
    }
    float wv[NHOP];
    float prod = 1.f, Ac = 0.f;
    #pragma unroll
    for (int k = NHOP-1; k >= 0; k--) {
        float wk = uw[k] * prod;
        wv[k] = wk;
        Ac += wk;
        prod *= (1.f - uw[k]);
    }
    if (lane == 0) { out_rem[m] = rem; out_nup[m] = nup; }

    // write scaled split A
    __half* dst = g_Asplit + (size_t)m * K2;
    #pragma unroll
    for (int seg = 0; seg < 8; seg++) {
        float4 b = bx[seg];
        __half hi[4], lo[4];
        hsplit(Ac*b.x, hi[0], lo[0]);
        hsplit(Ac*b.y, hi[1], lo[1]);
        hsplit(Ac*b.z, hi[2], lo[2]);
        hsplit(Ac*b.w, hi[3], lo[3]);
        *(uint2*)(dst + seg*128 + lane*4)        = *(uint2*)hi;
        *(uint2*)(dst + HH + seg*128 + lane*4)   = *(uint2*)lo;
    }
    // ext: 2 entries per lane
    {
        __half v0 = __float2half_rn(0.f), v1 = __float2half_rn(0.f);
        int j = lane;
        if (j < 12) v0 = __float2half_rn(wv[j]);
        else if (j < 24) {
            float w = wv[j-12];
            __half h = __float2half_rn(w);
            v0 = __float2half_rn(w - __half2float(h));
        } else {
            v0 = __float2half_rn(wv[j-24]);
        }
        int j2 = lane + 32;
        if (j2 < 36) v1 = __float2half_rn(wv[j2-24]);
        dst[KSPL + j]  = v0;
        dst[KSPL + j2] = v1;
    }
}

// ======================= kernel 2: fp16 mma.sync GEMM =======================
// out[m,n] = sum_k A_ext[m,k] * B_ext[n,k]   (256x128 CTA tile, 64x64 warp tile)

#define TM 256
#define TN 128
#define ROWB 144                        // padded row bytes: 64 fp16 = 128B + 16B pad
#define ABYTES (TM * ROWB)              // 36864
#define BBYTES (TN * ROWB)              // 18432
#define SMEM_GEMM (2*ABYTES + 2*BBYTES) // 110592

__device__ __forceinline__ void load_tiles(uint32_t sa, int buf, int kt, int bm, int bn, int tid) {
    const __half* Ab = g_Asplit + (size_t)bm * K2 + kt * KT;
    uint32_t adst = sa + buf * ABYTES;
    #pragma unroll
    for (int i = 0; i < 8; i++) {
        int id = tid + i * 256;
        int row = id >> 3, cc = id & 7;
        cp16(adst + row * ROWB + cc * 16, Ab + (size_t)row * K2 + cc * 8);
    }
    const __half* Bb = g_Bsplit + (size_t)bn * K2 + kt * KT;
    uint32_t bdst = sa + 2 * ABYTES + buf * BBYTES;
    #pragma unroll
    for (int i = 0; i < 4; i++) {
        int id = tid + i * 256;
        int row = id >> 3, cc = id & 7;
        cp16(bdst + row * ROWB + cc * 16, Bb + (size_t)row * K2 + cc * 8);
    }
    CP_COMMIT();
}

__global__ __launch_bounds__(256, 1)
void gemm_mma_kernel(float* __restrict__ outp) {
    extern __shared__ char smem[];
    uint32_t sa = smem_u32(smem);
    const int tid = threadIdx.x;
    const int lane = tid & 31;
    const int warp = tid >> 5;
    const int wm = (warp & 3) * 64;    // 4 warps along M
    const int wn = (warp >> 2) * 64;   // 2 warps along N
    const int bm = blockIdx.y * TM;
    const int bn = blockIdx.x * TN;

    const int g = lane >> 3, r = lane & 7;
    const uint32_t a_lm = sa + (uint32_t)((wm + (g & 1) * 8 + r) * ROWB + (g >> 1) * 16);
    const uint32_t b_lm = sa + 2 * ABYTES + (uint32_t)((wn + (g >> 1) * 8 + r) * ROWB + (g & 1) * 16);

    float acc[4][4][8];
    #pragma unroll
    for (int i = 0; i < 4; i++)
        #pragma unroll
        for (int j = 0; j < 4; j++)
            #pragma unroll
            for (int q = 0; q < 8; q++) acc[i][j][q] = 0.f;

    load_tiles(sa, 0, 0, bm, bn, tid);

    for (int kt = 0; kt < NT; kt++) {
        const int cur = kt & 1;
        if (kt + 1 < NT) {
            load_tiles(sa, cur ^ 1, kt + 1, bm, bn, tid);
            asm volatile("cp.async.wait_group 1;" ::: "memory");
        } else {
            asm volatile("cp.async.wait_group 0;" ::: "memory");
        }
        __syncthreads();

        const uint32_t abuf = a_lm + cur * ABYTES;
        const uint32_t bbuf = b_lm + cur * BBYTES;

        uint32_t af[2][4][4], bf[2][4][4];
        #pragma unroll
        for (int mf = 0; mf < 4; mf++) LDSM4(af[0][mf], abuf + mf * (16 * ROWB));
        #pragma unroll
        for (int nf = 0; nf < 4; nf++) LDSM4(bf[0][nf], bbuf + nf * (16 * ROWB));

        #pragma unroll
        for (int ks = 0; ks < 4; ks++) {
            const int cf = ks & 1;
            if (ks < 3) {
                const int pf = cf ^ 1;
                #pragma unroll
                for (int mf = 0; mf < 4; mf++)
                    LDSM4(af[pf][mf], abuf + mf * (16 * ROWB) + (ks + 1) * 32);
                #pragma unroll
                for (int nf = 0; nf < 4; nf++)
                    LDSM4(bf[pf][nf], bbuf + nf * (16 * ROWB) + (ks + 1) * 32);
            }
            #pragma unroll
            for (int mf = 0; mf < 4; mf++)
                #pragma unroll
                for (int nf = 0; nf < 4; nf++) {
                    MMA16816(acc[mf][nf] + 0, af[cf][mf], bf[cf][nf][0], bf[cf][nf][1]);
                    MMA16816(acc[mf][nf] + 4, af[cf][mf], bf[cf][nf][2], bf[cf][nf][3]);
                }
        }
        __syncthreads();
    }

    // store
    #pragma unroll
    for (int mf = 0; mf < 4; mf++) {
        #pragma unroll
        for (int nf = 0; nf < 4; nf++) {
            const int row0 = bm + wm + mf * 16 + (lane >> 2);
            const int col0 = bn + wn + nf * 16 + (lane & 3) * 2;
            float* p = outp + (size_t)row0 * HH + col0;
            *(float2*)(p)              = make_float2(acc[mf][nf][0], acc[mf][nf][1]);
            *(float2*)(p + 8*HH)       = make_float2(acc[mf][nf][2], acc[mf][nf][3]);
            *(float2*)(p + 8)          = make_float2(acc[mf][nf][4], acc[mf][nf][5]);
            *(float2*)(p + 8*HH + 8)   = make_float2(acc[mf][nf][6], acc[mf][nf][7]);
        }
    }
}

// ======================= host launch =======================
extern "C" void kernel_launch(void* const* d_in, const int* in_sizes, int n_in,
                              void* d_out, int out_size) {
    const float* inp   = (const float*)d_in[0];
    const float* tenc  = (const float*)d_in[1];
    const float* pos   = (const float*)d_in[2];
    const float* gamma = (const float*)d_in[3];
    const float* beta  = (const float*)d_in[4];
    const float* wp    = (const float*)d_in[5];
    const float* bp    = (const float*)d_in[6];
    const float* Wt    = (const float*)d_in[7];
    const float* bt    = (const float*)d_in[8];

    float* outp    = (float*)d_out;
    float* out_rem = outp + (size_t)MM * HH;
    float* out_nup = out_rem + MM;

    cudaFuncSetAttribute(gemm_mma_kernel, cudaFuncAttributeMaxDynamicSharedMemorySize, SMEM_GEMM);

    const_kernel<<<NHOP + 1, 256>>>(pos, gamma, beta, wp, bp);
    ck_kernel<<<HH, 128>>>(pos, Wt, bt);
    splitB_kernel<<<HH, 256>>>(Wt);
    token_stats_kernel<<<MM / 8, 256>>>(inp, tenc, pos, out_rem, out_nup);
    gemm_mma_kernel<<<dim3(HH / TN, MM / TM), 256, SMEM_GEMM>>>(outp);
}

// round 5
// speedup vs baseline: 2.8413x; 1.0453x over previous
#include <cuda_runtime.h>
#include <cuda_fp16.h>
#include <cstdint>
#include <cstddef>

// Problem constants
#define BB 8
#define TT 2048
#define HH 1024
#define MM (BB*TT)        // 16384
#define NHOP 12
#define THRESH 0.9f
#define LNEPS 1e-5f

// 1-term fp16 GEMM: [ahi] x [bhi] + 64 ext cols (36 used for exact rank-12 epilogue)
#define KSPL 1024
#define KEXT 64
#define K2   (KSPL + KEXT)   // 1088
#define KT   64              // fp16 per k-tile
#define NT   (K2 / KT)       // 17

// -------- device scratch (static, no runtime allocation) --------
__device__ __half g_Asplit[(size_t)MM * K2];   // ~35.7 MB
__device__ __half g_Bsplit[(size_t)HH * K2];   // ~2.2 MB
__device__ float g_gw[HH];                     // gamma*wp
__device__ float g_spk[NHOP];
__device__ float g_mupos[NHOP];
__device__ float g_qpos[NHOP];
__device__ float g_C0;
__device__ float g_G;

// ======================= helpers =======================
__device__ __forceinline__ uint32_t smem_u32(const void* p) {
    uint32_t a;
    asm("{ .reg .u64 t; cvta.to.shared.u64 t, %1; cvt.u32.u64 %0, t; }" : "=r"(a) : "l"(p));
    return a;
}

__device__ __forceinline__ void cp16(uint32_t dst, const void* src) {
    asm volatile("cp.async.cg.shared.global [%0], [%1], 16;" :: "r"(dst), "l"(src));
}
#define CP_COMMIT() asm volatile("cp.async.commit_group;" ::: "memory")

#define LDSM4(R, addr) \
    asm volatile("ldmatrix.sync.aligned.m8n8.x4.shared.b16 {%0,%1,%2,%3}, [%4];" \
        : "=r"((R)[0]), "=r"((R)[1]), "=r"((R)[2]), "=r"((R)[3]) : "r"(addr))

#define MMA16816(C, A, b0, b1) \
    asm volatile("mma.sync.aligned.m16n8k16.row.col.f32.f16.f16.f32 " \
        "{%0,%1,%2,%3}, {%4,%5,%6,%7}, {%8,%9}, {%0,%1,%2,%3};" \
        : "+f"((C)[0]), "+f"((C)[1]), "+f"((C)[2]), "+f"((C)[3]) \
        : "r"((A)[0]), "r"((A)[1]), "r"((A)[2]), "r"((A)[3]), "r"(b0), "r"(b1))

__device__ __forceinline__ float warpReduce(float v) {
    #pragma unroll
    for (int o = 16; o > 0; o >>= 1) v += __shfl_xor_sync(0xffffffffu, v, o);
    return v;
}
__device__ __forceinline__ float dot4(float4 a, float4 b) {
    return a.x*b.x + a.y*b.y + a.z*b.z + a.w*b.w;
}

// ======================= kernel 0a: per-hop scalar constants + gw =======================
__global__ void const_kernel(const float* __restrict__ pos,
                             const float* __restrict__ gamma,
                             const float* __restrict__ beta,
                             const float* __restrict__ wp,
                             const float* __restrict__ bp) {
    const int bid = blockIdx.x;
    const int tid = threadIdx.x;
    __shared__ float red[3][8];
    const int lane = tid & 31, wid = tid >> 5;
    if (bid < NHOP) {
        float sp = 0.f, mp = 0.f, qp = 0.f;
        for (int h = tid; h < HH; h += 256) {
            float pv = pos[bid*HH + h];
            sp += pv * gamma[h] * wp[h];
            mp += pv;
            qp += pv * pv;
        }
        sp = warpReduce(sp); mp = warpReduce(mp); qp = warpReduce(qp);
        if (lane == 0) { red[0][wid] = sp; red[1][wid] = mp; red[2][wid] = qp; }
        __syncthreads();
        if (tid == 0) {
            float s = 0.f, m = 0.f, q = 0.f;
            #pragma unroll
            for (int i = 0; i < 8; i++) { s += red[0][i]; m += red[1][i]; q += red[2][i]; }
            g_spk[bid] = s;
            g_mupos[bid] = m * (1.f / HH);
            g_qpos[bid] = q * (1.f / HH);
        }
    } else {
        float c0 = 0.f, g = 0.f;
        for (int h = tid; h < HH; h += 256) {
            float gw = gamma[h] * wp[h];
            g_gw[h] = gw;
            c0 += beta[h] * wp[h];
            g  += gw;
        }
        c0 = warpReduce(c0); g = warpReduce(g);
        if (lane == 0) { red[0][wid] = c0; red[1][wid] = g; }
        __syncthreads();
        if (tid == 0) {
            float s = 0.f, s2 = 0.f;
            #pragma unroll
            for (int i = 0; i < 8; i++) { s += red[0][i]; s2 += red[1][i]; }
            g_C0 = s + bp[0];
            g_G = s2;
        }
    }
}

// ============ kernel 0b: build B_ext rows (fused c_k computation) ============
// B row n: [0:1024)=hi(Wt[n]); ext: [0:12)=c_hi, [12:24)=c_hi, [24:36)=c_lo, rest 0
// where c_k[n] = pos_k . Wt[n] + bt[n]
__global__ __launch_bounds__(256)
void splitB_kernel(const float* __restrict__ pos,
                   const float* __restrict__ Wt,
                   const float* __restrict__ bt) {
    const int o = blockIdx.x;
    const int tid = threadIdx.x;
    const int lane = tid & 31, wid = tid >> 5;
    __half* dst = g_Bsplit + (size_t)o * K2;

    float4 v = ((const float4*)(Wt + (size_t)o * HH))[tid];
    {
        __half hi[4];
        hi[0] = __float2half_rn(v.x);
        hi[1] = __float2half_rn(v.y);
        hi[2] = __float2half_rn(v.z);
        hi[3] = __float2half_rn(v.w);
        *(uint2*)(dst + 4*tid) = *(uint2*)hi;
    }

    // c_k[o] = pos_k . Wt[o]
    const float4* p4 = (const float4*)pos;
    float acc[NHOP];
    #pragma unroll
    for (int k = 0; k < NHOP; k++)
        acc[k] = dot4(v, p4[k*(HH/4) + tid]);

    __shared__ float red[NHOP][8];
    __shared__ float c_s[NHOP];
    #pragma unroll
    for (int k = 0; k < NHOP; k++) {
        float r = warpReduce(acc[k]);
        if (lane == 0) red[k][wid] = r;
    }
    __syncthreads();
    if (tid < NHOP) {
        float s = 0.f;
        #pragma unroll
        for (int i = 0; i < 8; i++) s += red[tid][i];
        c_s[tid] = s + bt[o];
    }
    __syncthreads();

    if (tid < KEXT) {
        __half val = __float2half_rn(0.f);
        if (tid < 24) {
            int k = (tid < 12) ? tid : tid - 12;
            val = __float2half_rn(c_s[k]);
        } else if (tid < 36) {
            float c = c_s[tid-24];
            __half h = __float2half_rn(c);
            val = __float2half_rn(c - __half2float(h));
        }
        dst[KSPL + tid] = val;
    }
}

// ========= kernel 1: warp-per-token stats + ACT + scaled A write (fused) =========
// A row m: [0:1024)=hi(Ac*base); ext: [0:12)=w_hi, [12:24)=w_lo, [24:36)=w_hi, rest 0
__global__ __launch_bounds__(256)
void token_stats_kernel(const float* __restrict__ inp,
                        const float* __restrict__ tenc,
                        const float* __restrict__ pos,
                        float* __restrict__ out_rem,
                        float* __restrict__ out_nup) {
    const int warp = threadIdx.x >> 5;
    const int lane = threadIdx.x & 31;
    const int m = blockIdx.x * 8 + warp;

    const float4* in4 = (const float4*)inp + (size_t)m * (HH/4);
    const float4* t4p = (const float4*)tenc + (size_t)(m & (TT-1)) * (HH/4);
    const float4* gw4 = (const float4*)g_gw;
    const float4* p4  = (const float4*)pos;

    float4 bx[8];
    float s0 = 0.f, s1 = 0.f, s2 = 0.f;
    #pragma unroll
    for (int seg = 0; seg < 8; seg++) {
        float4 a = in4[seg*32 + lane];
        float4 t = t4p[seg*32 + lane];
        float4 b = make_float4(a.x+t.x, a.y+t.y, a.z+t.z, a.w+t.w);
        bx[seg] = b;
        s0 += b.x + b.y + b.z + b.w;
        s1 += dot4(b, b);
        s2 += dot4(b, gw4[seg*32 + lane]);
    }
    float sp[NHOP];
    #pragma unroll
    for (int k = 0; k < NHOP; k++) {
        float a = 0.f;
        #pragma unroll
        for (int seg = 0; seg < 8; seg++)
            a += dot4(bx[seg], p4[k*(HH/4) + seg*32 + lane]);
        sp[k] = a;
    }

    // xor-reduce: all lanes end with totals
    s0 = warpReduce(s0); s1 = warpReduce(s1); s2 = warpReduce(s2);
    #pragma unroll
    for (int k = 0; k < NHOP; k++) sp[k] = warpReduce(sp[k]);

    // ACT recurrence (redundant on all lanes)
    const float mu_b = s0 * (1.f / HH);
    const float q_b  = s1 * (1.f / HH);
    const float G = g_G, C0 = g_C0;

    float hp = 0.f, rem = 0.f, nup = 0.f;
    float uw[NHOP];
    #pragma unroll
    for (int k = 0; k < NHOP; k++) {
        float mu  = mu_b + g_mupos[k];
        float ex2 = q_b + 2.f * sp[k] * (1.f / HH) + g_qpos[k];
        float var = ex2 - mu * mu;
        float Sg  = s2 + g_spk[k];
        float logit = rsqrtf(var + LNEPS) * (Sg - mu * G) + C0;
        float p = 1.f / (1.f + expf(-logit));

        float sr  = (hp < 1.f) ? 1.f : 0.f;
        float acc = hp + p * sr;
        float nh  = (acc > THRESH) ? sr : 0.f;
        sr        = (acc <= THRESH) ? sr : 0.f;
        hp  = hp + p * sr;
        rem = rem + nh * (1.f - hp);
        hp  = hp + nh * rem;
        nup = nup + sr + nh;
        uw[k] = p * sr + nh * rem;
    }
    float wv[NHOP];
    float prod = 1.f, Ac = 0.f;
    #pragma unroll
    for (int k = NHOP-1; k >= 0; k--) {
        float wk = uw[k] * prod;
        wv[k] = wk;
        Ac += wk;
        prod *= (1.f - uw[k]);
    }
    if (lane == 0) { out_rem[m] = rem; out_nup[m] = nup; }

    // write scaled hi-split A
    __half* dst = g_Asplit + (size_t)m * K2;
    #pragma unroll
    for (int seg = 0; seg < 8; seg++) {
        float4 b = bx[seg];
        __half hi[4];
        hi[0] = __float2half_rn(Ac*b.x);
        hi[1] = __float2half_rn(Ac*b.y);
        hi[2] = __float2half_rn(Ac*b.z);
        hi[3] = __float2half_rn(Ac*b.w);
        *(uint2*)(dst + seg*128 + lane*4) = *(uint2*)hi;
    }
    // ext: 2 entries per lane
    {
        __half v0 = __float2half_rn(0.f), v1 = __float2half_rn(0.f);
        int j = lane;
        if (j < 12) v0 = __float2half_rn(wv[j]);
        else if (j < 24) {
            float w = wv[j-12];
            __half h = __float2half_rn(w);
            v0 = __float2half_rn(w - __half2float(h));
        } else {
            v0 = __float2half_rn(wv[j-24]);
        }
        int j2 = lane + 32;
        if (j2 < 36) v1 = __float2half_rn(wv[j2-24]);
        dst[KSPL + j]  = v0;
        dst[KSPL + j2] = v1;
    }
}

// ======================= kernel 2: fp16 mma.sync GEMM =======================
// out[m,n] = sum_k A_ext[m,k] * B_ext[n,k]   (256x128 CTA tile, 64x64 warp tile)

#define TM 256
#define TN 128
#define ROWB 144                        // padded row bytes: 64 fp16 = 128B + 16B pad
#define ABYTES (TM * ROWB)              // 36864
#define BBYTES (TN * ROWB)              // 18432
#define SMEM_GEMM (2*ABYTES + 2*BBYTES) // 110592

__device__ __forceinline__ void load_tiles(uint32_t sa, int buf, int kt, int bm, int bn, int tid) {
    const __half* Ab = g_Asplit + (size_t)bm * K2 + kt * KT;
    uint32_t adst = sa + buf * ABYTES;
    #pragma unroll
    for (int i = 0; i < 8; i++) {
        int id = tid + i * 256;
        int row = id >> 3, cc = id & 7;
        cp16(adst + row * ROWB + cc * 16, Ab + (size_t)row * K2 + cc * 8);
    }
    const __half* Bb = g_Bsplit + (size_t)bn * K2 + kt * KT;
    uint32_t bdst = sa + 2 * ABYTES + buf * BBYTES;
    #pragma unroll
    for (int i = 0; i < 4; i++) {
        int id = tid + i * 256;
        int row = id >> 3, cc = id & 7;
        cp16(bdst + row * ROWB + cc * 16, Bb + (size_t)row * K2 + cc * 8);
    }
    CP_COMMIT();
}

__global__ __launch_bounds__(256, 1)
void gemm_mma_kernel(float* __restrict__ outp) {
    extern __shared__ char smem[];
    uint32_t sa = smem_u32(smem);
    const int tid = threadIdx.x;
    const int lane = tid & 31;
    const int warp = tid >> 5;
    const int wm = (warp & 3) * 64;    // 4 warps along M
    const int wn = (warp >> 2) * 64;   // 2 warps along N
    const int bm = blockIdx.y * TM;
    const int bn = blockIdx.x * TN;

    const int g = lane >> 3, r = lane & 7;
    const uint32_t a_lm = sa + (uint32_t)((wm + (g & 1) * 8 + r) * ROWB + (g >> 1) * 16);
    const uint32_t b_lm = sa + 2 * ABYTES + (uint32_t)((wn + (g >> 1) * 8 + r) * ROWB + (g & 1) * 16);

    float acc[4][4][8];
    #pragma unroll
    for (int i = 0; i < 4; i++)
        #pragma unroll
        for (int j = 0; j < 4; j++)
            #pragma unroll
            for (int q = 0; q < 8; q++) acc[i][j][q] = 0.f;

    load_tiles(sa, 0, 0, bm, bn, tid);

    for (int kt = 0; kt < NT; kt++) {
        const int cur = kt & 1;
        if (kt + 1 < NT) {
            load_tiles(sa, cur ^ 1, kt + 1, bm, bn, tid);
            asm volatile("cp.async.wait_group 1;" ::: "memory");
        } else {
            asm volatile("cp.async.wait_group 0;" ::: "memory");
        }
        __syncthreads();

        const uint32_t abuf = a_lm + cur * ABYTES;
        const uint32_t bbuf = b_lm + cur * BBYTES;

        uint32_t af[2][4][4], bf[2][4][4];
        #pragma unroll
        for (int mf = 0; mf < 4; mf++) LDSM4(af[0][mf], abuf + mf * (16 * ROWB));
        #pragma unroll
        for (int nf = 0; nf < 4; nf++) LDSM4(bf[0][nf], bbuf + nf * (16 * ROWB));

        #pragma unroll
        for (int ks = 0; ks < 4; ks++) {
            const int cf = ks & 1;
            if (ks < 3) {
                const int pf = cf ^ 1;
                #pragma unroll
                for (int mf = 0; mf < 4; mf++)
                    LDSM4(af[pf][mf], abuf + mf * (16 * ROWB) + (ks + 1) * 32);
                #pragma unroll
                for (int nf = 0; nf < 4; nf++)
                    LDSM4(bf[pf][nf], bbuf + nf * (16 * ROWB) + (ks + 1) * 32);
            }
            #pragma unroll
            for (int mf = 0; mf < 4; mf++)
                #pragma unroll
                for (int nf = 0; nf < 4; nf++) {
                    MMA16816(acc[mf][nf] + 0, af[cf][mf], bf[cf][nf][0], bf[cf][nf][1]);
                    MMA16816(acc[mf][nf] + 4, af[cf][mf], bf[cf][nf][2], bf[cf][nf][3]);
                }
        }
        __syncthreads();
    }

    // store
    #pragma unroll
    for (int mf = 0; mf < 4; mf++) {
        #pragma unroll
        for (int nf = 0; nf < 4; nf++) {
            const int row0 = bm + wm + mf * 16 + (lane >> 2);
            const int col0 = bn + wn + nf * 16 + (lane & 3) * 2;
            float* p = outp + (size_t)row0 * HH + col0;
            *(float2*)(p)              = make_float2(acc[mf][nf][0], acc[mf][nf][1]);
            *(float2*)(p + 8*HH)       = make_float2(acc[mf][nf][2], acc[mf][nf][3]);
            *(float2*)(p + 8)          = make_float2(acc[mf][nf][4], acc[mf][nf][5]);
            *(float2*)(p + 8*HH + 8)   = make_float2(acc[mf][nf][6], acc[mf][nf][7]);
        }
    }
}

// ======================= host launch =======================
extern "C" void kernel_launch(void* const* d_in, const int* in_sizes, int n_in,
                              void* d_out, int out_size) {
    const float* inp   = (const float*)d_in[0];
    const float* tenc  = (const float*)d_in[1];
    const float* pos   = (const float*)d_in[2];
    const float* gamma = (const float*)d_in[3];
    const float* beta  = (const float*)d_in[4];
    const float* wp    = (const float*)d_in[5];
    const float* bp    = (const float*)d_in[6];
    const float* Wt    = (const float*)d_in[7];
    const float* bt    = (const float*)d_in[8];

    float* outp    = (float*)d_out;
    float* out_rem = outp + (size_t)MM * HH;
    float* out_nup = out_rem + MM;

    cudaFuncSetAttribute(gemm_mma_kernel, cudaFuncAttributeMaxDynamicSharedMemorySize, SMEM_GEMM);

    const_kernel<<<NHOP + 1, 256>>>(pos, gamma, beta, wp, bp);
    splitB_kernel<<<HH, 256>>>(pos, Wt, bt);
    token_stats_kernel<<<MM / 8, 256>>>(inp, tenc, pos, out_rem, out_nup);
    gemm_mma_kernel<<<dim3(HH / TN, MM / TM), 256, SMEM_GEMM>>>(outp);
}

// round 6
// speedup vs baseline: 4.7714x; 1.6793x over previous
#include <cuda_runtime.h>
#include <cuda_fp16.h>
#include <cstdint>
#include <cstddef>

// Problem constants
#define BB 8
#define TT 2048
#define HH 1024
#define MM (BB*TT)        // 16384
#define NHOP 12
#define THRESH 0.9f
#define LNEPS 1e-5f

// 1-term fp16 GEMM: [ahi] x [bhi] + 64 ext cols (36 used for exact rank-12 epilogue)
#define KSPL 1024
#define KEXT 64
#define K2   (KSPL + KEXT)   // 1088
#define KT   64              // fp16 per k-tile
#define NT   (K2 / KT)       // 17

// -------- device scratch (static, no runtime allocation) --------
__device__ __half g_Asplit[(size_t)MM * K2];   // ~35.7 MB
__device__ __half g_Bsplit[(size_t)HH * K2];   // ~2.2 MB
__device__ float g_gw[HH];                     // gamma*wp
__device__ float g_spk[NHOP];
__device__ float g_mupos[NHOP];
__device__ float g_qpos[NHOP];
__device__ float g_C0;
__device__ float g_G;

// ======================= helpers =======================
__device__ __forceinline__ uint32_t smem_u32(const void* p) {
    uint32_t a;
    asm("{ .reg .u64 t; cvta.to.shared.u64 t, %1; cvt.u32.u64 %0, t; }" : "=r"(a) : "l"(p));
    return a;
}

__device__ __forceinline__ void cp16(uint32_t dst, const void* src) {
    asm volatile("cp.async.cg.shared.global [%0], [%1], 16;" :: "r"(dst), "l"(src));
}
#define CP_COMMIT() asm volatile("cp.async.commit_group;" ::: "memory")

#define LDSM4(R, addr) \
    asm volatile("ldmatrix.sync.aligned.m8n8.x4.shared.b16 {%0,%1,%2,%3}, [%4];" \
        : "=r"((R)[0]), "=r"((R)[1]), "=r"((R)[2]), "=r"((R)[3]) : "r"(addr))

#define MMA16816(C, A, b0, b1) \
    asm volatile("mma.sync.aligned.m16n8k16.row.col.f32.f16.f16.f32 " \
        "{%0,%1,%2,%3}, {%4,%5,%6,%7}, {%8,%9}, {%0,%1,%2,%3};" \
        : "+f"((C)[0]), "+f"((C)[1]), "+f"((C)[2]), "+f"((C)[3]) \
        : "r"((A)[0]), "r"((A)[1]), "r"((A)[2]), "r"((A)[3]), "r"(b0), "r"(b1))

__device__ __forceinline__ float warpReduce(float v) {
    #pragma unroll
    for (int o = 16; o > 0; o >>= 1) v += __shfl_xor_sync(0xffffffffu, v, o);
    return v;
}
__device__ __forceinline__ float dot4(float4 a, float4 b) {
    return a.x*b.x + a.y*b.y + a.z*b.z + a.w*b.w;
}

// ======================= kernel 0a: per-hop scalar constants + gw =======================
__global__ void const_kernel(const float* __restrict__ pos,
                             const float* __restrict__ gamma,
                             const float* __restrict__ beta,
                             const float* __restrict__ wp,
                             const float* __restrict__ bp) {
    const int bid = blockIdx.x;
    const int tid = threadIdx.x;
    __shared__ float red[3][8];
    const int lane = tid & 31, wid = tid >> 5;
    if (bid < NHOP) {
        float sp = 0.f, mp = 0.f, qp = 0.f;
        for (int h = tid; h < HH; h += 256) {
            float pv = pos[bid*HH + h];
            sp += pv * gamma[h] * wp[h];
            mp += pv;
            qp += pv * pv;
        }
        sp = warpReduce(sp); mp = warpReduce(mp); qp = warpReduce(qp);
        if (lane == 0) { red[0][wid] = sp; red[1][wid] = mp; red[2][wid] = qp; }
        __syncthreads();
        if (tid == 0) {
            float s = 0.f, m = 0.f, q = 0.f;
            #pragma unroll
            for (int i = 0; i < 8; i++) { s += red[0][i]; m += red[1][i]; q += red[2][i]; }
            g_spk[bid] = s;
            g_mupos[bid] = m * (1.f / HH);
            g_qpos[bid] = q * (1.f / HH);
        }
    } else {
        float c0 = 0.f, g = 0.f;
        for (int h = tid; h < HH; h += 256) {
            float gw = gamma[h] * wp[h];
            g_gw[h] = gw;
            c0 += beta[h] * wp[h];
            g  += gw;
        }
        c0 = warpReduce(c0); g = warpReduce(g);
        if (lane == 0) { red[0][wid] = c0; red[1][wid] = g; }
        __syncthreads();
        if (tid == 0) {
            float s = 0.f, s2 = 0.f;
            #pragma unroll
            for (int i = 0; i < 8; i++) { s += red[0][i]; s2 += red[1][i]; }
            g_C0 = s + bp[0];
            g_G = s2;
        }
    }
}

// ============ kernel 0b: build B_ext rows (fused c_k computation) ============
// B row n: [0:1024)=hi(Wt[n]); ext: [0:12)=c_hi, [12:24)=c_hi, [24:36)=c_lo, rest 0
__global__ __launch_bounds__(256)
void splitB_kernel(const float* __restrict__ pos,
                   const float* __restrict__ Wt,
                   const float* __restrict__ bt) {
    const int o = blockIdx.x;
    const int tid = threadIdx.x;
    const int lane = tid & 31, wid = tid >> 5;
    __half* dst = g_Bsplit + (size_t)o * K2;

    float4 v = ((const float4*)(Wt + (size_t)o * HH))[tid];
    {
        __half hi[4];
        hi[0] = __float2half_rn(v.x);
        hi[1] = __float2half_rn(v.y);
        hi[2] = __float2half_rn(v.z);
        hi[3] = __float2half_rn(v.w);
        *(uint2*)(dst + 4*tid) = *(uint2*)hi;
    }

    const float4* p4 = (const float4*)pos;
    float acc[NHOP];
    #pragma unroll
    for (int k = 0; k < NHOP; k++)
        acc[k] = dot4(v, p4[k*(HH/4) + tid]);

    __shared__ float red[NHOP][8];
    __shared__ float c_s[NHOP];
    #pragma unroll
    for (int k = 0; k < NHOP; k++) {
        float r = warpReduce(acc[k]);
        if (lane == 0) red[k][wid] = r;
    }
    __syncthreads();
    if (tid < NHOP) {
        float s = 0.f;
        #pragma unroll
        for (int i = 0; i < 8; i++) s += red[tid][i];
        c_s[tid] = s + bt[o];
    }
    __syncthreads();

    if (tid < KEXT) {
        __half val = __float2half_rn(0.f);
        if (tid < 24) {
            int k = (tid < 12) ? tid : tid - 12;
            val = __float2half_rn(c_s[k]);
        } else if (tid < 36) {
            float c = c_s[tid-24];
            __half h = __float2half_rn(c);
            val = __float2half_rn(c - __half2float(h));
        }
        dst[KSPL + tid] = val;
    }
}

// ========= kernel 1: warp-per-token stats + ACT + scaled A write (fused) =========
__global__ __launch_bounds__(256)
void token_stats_kernel(const float* __restrict__ inp,
                        const float* __restrict__ tenc,
                        const float* __restrict__ pos,
                        float* __restrict__ out_rem,
                        float* __restrict__ out_nup) {
    const int warp = threadIdx.x >> 5;
    const int lane = threadIdx.x & 31;
    const int m = blockIdx.x * 8 + warp;

    const float4* in4 = (const float4*)inp + (size_t)m * (HH/4);
    const float4* t4p = (const float4*)tenc + (size_t)(m & (TT-1)) * (HH/4);
    const float4* gw4 = (const float4*)g_gw;
    const float4* p4  = (const float4*)pos;

    float4 bx[8];
    float s0 = 0.f, s1 = 0.f, s2 = 0.f;
    #pragma unroll
    for (int seg = 0; seg < 8; seg++) {
        float4 a = in4[seg*32 + lane];
        float4 t = t4p[seg*32 + lane];
        float4 b = make_float4(a.x+t.x, a.y+t.y, a.z+t.z, a.w+t.w);
        bx[seg] = b;
        s0 += b.x + b.y + b.z + b.w;
        s1 += dot4(b, b);
        s2 += dot4(b, gw4[seg*32 + lane]);
    }
    float sp[NHOP];
    #pragma unroll
    for (int k = 0; k < NHOP; k++) {
        float a = 0.f;
        #pragma unroll
        for (int seg = 0; seg < 8; seg++)
            a += dot4(bx[seg], p4[k*(HH/4) + seg*32 + lane]);
        sp[k] = a;
    }

    s0 = warpReduce(s0); s1 = warpReduce(s1); s2 = warpReduce(s2);
    #pragma unroll
    for (int k = 0; k < NHOP; k++) sp[k] = warpReduce(sp[k]);

    const float mu_b = s0 * (1.f / HH);
    const float q_b  = s1 * (1.f / HH);
    const float G = g_G, C0 = g_C0;

    float hp = 0.f, rem = 0.f, nup = 0.f;
    float uw[NHOP];
    #pragma unroll
    for (int k = 0; k < NHOP; k++) {
        float mu  = mu_b + g_mupos[k];
        float ex2 = q_b + 2.f * sp[k] * (1.f / HH) + g_qpos[k];
        float var = ex2 - mu * mu;
        float Sg  = s2 + g_spk[k];
        float logit = rsqrtf(var + LNEPS) * (Sg - mu * G) + C0;
        float p = 1.f / (1.f + expf(-logit));

        float sr  = (hp < 1.f) ? 1.f : 0.f;
        float acc = hp + p * sr;
        float nh  = (acc > THRESH) ? sr : 0.f;
        sr        = (acc <= THRESH) ? sr : 0.f;
        hp  = hp + p * sr;
        rem = rem + nh * (1.f - hp);
        hp  = hp + nh * rem;
        nup = nup + sr + nh;
        uw[k] = p * sr + nh * rem;
    }
    float wv[NHOP];
    float prod = 1.f, Ac = 0.f;
    #pragma unroll
    for (int k = NHOP-1; k >= 0; k--) {
        float wk = uw[k] * prod;
        wv[k] = wk;
        Ac += wk;
        prod *= (1.f - uw[k]);
    }
    if (lane == 0) { out_rem[m] = rem; out_nup[m] = nup; }

    __half* dst = g_Asplit + (size_t)m * K2;
    #pragma unroll
    for (int seg = 0; seg < 8; seg++) {
        float4 b = bx[seg];
        __half hi[4];
        hi[0] = __float2half_rn(Ac*b.x);
        hi[1] = __float2half_rn(Ac*b.y);
        hi[2] = __float2half_rn(Ac*b.z);
        hi[3] = __float2half_rn(Ac*b.w);
        *(uint2*)(dst + seg*128 + lane*4) = *(uint2*)hi;
    }
    {
        __half v0 = __float2half_rn(0.f), v1 = __float2half_rn(0.f);
        int j = lane;
        if (j < 12) v0 = __float2half_rn(wv[j]);
        else if (j < 24) {
            float w = wv[j-12];
            __half h = __float2half_rn(w);
            v0 = __float2half_rn(w - __half2float(h));
        } else {
            v0 = __float2half_rn(wv[j-24]);
        }
        int j2 = lane + 32;
        if (j2 < 36) v1 = __float2half_rn(wv[j2-24]);
        dst[KSPL + j]  = v0;
        dst[KSPL + j2] = v1;
    }
}

// ======================= kernel 2: fp16 mma.sync GEMM =======================
// 128x128 CTA tile, 256 threads, warp grid 2(M) x 4(N), warp tile 64x32.
// 2 CTAs/SM for latency hiding (regs<=128, smem 73.7KB).

#define TM 128
#define TN 128
#define ROWB 144                        // padded row bytes: 64 fp16 = 128B + 16B pad
#define ABYTES (TM * ROWB)              // 18432
#define BBYTES (TN * ROWB)              // 18432
#define SMEM_GEMM (2*ABYTES + 2*BBYTES) // 73728

__device__ __forceinline__ void load_tiles(uint32_t sa, int buf, int kt, int bm, int bn, int tid) {
    const __half* Ab = g_Asplit + (size_t)bm * K2 + kt * KT;
    uint32_t adst = sa + buf * ABYTES;
    #pragma unroll
    for (int i = 0; i < 4; i++) {
        int id = tid + i * 256;
        int row = id >> 3, cc = id & 7;
        cp16(adst + row * ROWB + cc * 16, Ab + (size_t)row * K2 + cc * 8);
    }
    const __half* Bb = g_Bsplit + (size_t)bn * K2 + kt * KT;
    uint32_t bdst = sa + 2 * ABYTES + buf * BBYTES;
    #pragma unroll
    for (int i = 0; i < 4; i++) {
        int id = tid + i * 256;
        int row = id >> 3, cc = id & 7;
        cp16(bdst + row * ROWB + cc * 16, Bb + (size_t)row * K2 + cc * 8);
    }
    CP_COMMIT();
}

__global__ __launch_bounds__(256, 2)
void gemm_mma_kernel(float* __restrict__ outp) {
    extern __shared__ char smem[];
    uint32_t sa = smem_u32(smem);
    const int tid = threadIdx.x;
    const int lane = tid & 31;
    const int warp = tid >> 5;
    const int wm = (warp & 1) * 64;    // 2 warps along M (64 rows each)
    const int wn = (warp >> 1) * 32;   // 4 warps along N (32 cols each)
    const int bm = blockIdx.y * TM;
    const int bn = blockIdx.x * TN;

    const int g = lane >> 3, r = lane & 7;
    const uint32_t a_lm = sa + (uint32_t)((wm + (g & 1) * 8 + r) * ROWB + (g >> 1) * 16);
    const uint32_t b_lm = sa + 2 * ABYTES + (uint32_t)((wn + (g >> 1) * 8 + r) * ROWB + (g & 1) * 16);

    float acc[4][2][8];
    #pragma unroll
    for (int i = 0; i < 4; i++)
        #pragma unroll
        for (int j = 0; j < 2; j++)
            #pragma unroll
            for (int q = 0; q < 8; q++) acc[i][j][q] = 0.f;

    load_tiles(sa, 0, 0, bm, bn, tid);

    for (int kt = 0; kt < NT; kt++) {
        const int cur = kt & 1;
        if (kt + 1 < NT) {
            load_tiles(sa, cur ^ 1, kt + 1, bm, bn, tid);
            asm volatile("cp.async.wait_group 1;" ::: "memory");
        } else {
            asm volatile("cp.async.wait_group 0;" ::: "memory");
        }
        __syncthreads();

        const uint32_t abuf = a_lm + cur * ABYTES;
        const uint32_t bbuf = b_lm + cur * BBYTES;

        #pragma unroll
        for (int ks = 0; ks < 4; ks++) {
            uint32_t af[4][4];
            #pragma unroll
            for (int mf = 0; mf < 4; mf++)
                LDSM4(af[mf], abuf + mf * (16 * ROWB) + ks * 32);
            uint32_t bfr[2][4];
            #pragma unroll
            for (int nf = 0; nf < 2; nf++)
                LDSM4(bfr[nf], bbuf + nf * (16 * ROWB) + ks * 32);
            #pragma unroll
            for (int mf = 0; mf < 4; mf++)
                #pragma unroll
                for (int nf = 0; nf < 2; nf++) {
                    MMA16816(acc[mf][nf] + 0, af[mf], bfr[nf][0], bfr[nf][1]);
                    MMA16816(acc[mf][nf] + 4, af[mf], bfr[nf][2], bfr[nf][3]);
                }
        }
        __syncthreads();
    }

    // store
    #pragma unroll
    for (int mf = 0; mf < 4; mf++) {
        #pragma unroll
        for (int nf = 0; nf < 2; nf++) {
            const int row0 = bm + wm + mf * 16 + (lane >> 2);
            const int col0 = bn + wn + nf * 16 + (lane & 3) * 2;
            float* p = outp + (size_t)row0 * HH + col0;
            *(float2*)(p)              = make_float2(acc[mf][nf][0], acc[mf][nf][1]);
            *(float2*)(p + 8*HH)       = make_float2(acc[mf][nf][2], acc[mf][nf][3]);
            *(float2*)(p + 8)          = make_float2(acc[mf][nf][4], acc[mf][nf][5]);
            *(float2*)(p + 8*HH + 8)   = make_float2(acc[mf][nf][6], acc[mf][nf][7]);
        }
    }
}

// ======================= host launch =======================
extern "C" void kernel_launch(void* const* d_in, const int* in_sizes, int n_in,
                              void* d_out, int out_size) {
    const float* inp   = (const float*)d_in[0];
    const float* tenc  = (const float*)d_in[1];
    const float* pos   = (const float*)d_in[2];
    const float* gamma = (const float*)d_in[3];
    const float* beta  = (const float*)d_in[4];
    const float* wp    = (const float*)d_in[5];
    const float* bp    = (const float*)d_in[6];
    const float* Wt    = (const float*)d_in[7];
    const float* bt    = (const float*)d_in[8];

    float* outp    = (float*)d_out;
    float* out_rem = outp + (size_t)MM * HH;
    float* out_nup = out_rem + MM;

    cudaFuncSetAttribute(gemm_mma_kernel, cudaFuncAttributeMaxDynamicSharedMemorySize, SMEM_GEMM);

    const_kernel<<<NHOP + 1, 256>>>(pos, gamma, beta, wp, bp);
    splitB_kernel<<<HH, 256>>>(pos, Wt, bt);
    token_stats_kernel<<<MM / 8, 256>>>(inp, tenc, pos, out_rem, out_nup);
    gemm_mma_kernel<<<dim3(HH / TN, MM / TM), 256, SMEM_GEMM>>>(outp);
}

// round 7
// speedup vs baseline: 4.8796x; 1.0227x over previous
#include <cuda_runtime.h>
#include <cuda_fp16.h>
#include <cstdint>
#include <cstddef>

// Problem constants
#define BB 8
#define TT 2048
#define HH 1024
#define MM (BB*TT)        // 16384
#define NHOP 12
#define THRESH 0.9f
#define LNEPS 1e-5f

// 1-term fp16 GEMM: [ahi] x [bhi] + 64 ext cols (36 used for exact rank-12 epilogue)
#define KSPL 1024
#define KEXT 64
#define K2   (KSPL + KEXT)   // 1088
#define KT   64              // fp16 per k-tile
#define NT   (K2 / KT)       // 17

// -------- device scratch (static, no runtime allocation) --------
__device__ __half g_Asplit[(size_t)MM * K2];   // ~35.7 MB
__device__ __half g_Bsplit[(size_t)HH * K2];   // ~2.2 MB
__device__ float g_gw[HH];                     // gamma*wp
__device__ float g_spk[NHOP];
__device__ float g_mupos[NHOP];
__device__ float g_qpos[NHOP];
__device__ float g_C0;
__device__ float g_G;

// ======================= helpers =======================
__device__ __forceinline__ uint32_t smem_u32(const void* p) {
    uint32_t a;
    asm("{ .reg .u64 t; cvta.to.shared.u64 t, %1; cvt.u32.u64 %0, t; }" : "=r"(a) : "l"(p));
    return a;
}

__device__ __forceinline__ void cp16(uint32_t dst, const void* src) {
    asm volatile("cp.async.cg.shared.global [%0], [%1], 16;" :: "r"(dst), "l"(src));
}
#define CP_COMMIT() asm volatile("cp.async.commit_group;" ::: "memory")

#define LDSM4(R, addr) \
    asm volatile("ldmatrix.sync.aligned.m8n8.x4.shared.b16 {%0,%1,%2,%3}, [%4];" \
        : "=r"((R)[0]), "=r"((R)[1]), "=r"((R)[2]), "=r"((R)[3]) : "r"(addr))

#define MMA16816(C, A, b0, b1) \
    asm volatile("mma.sync.aligned.m16n8k16.row.col.f32.f16.f16.f32 " \
        "{%0,%1,%2,%3}, {%4,%5,%6,%7}, {%8,%9}, {%0,%1,%2,%3};" \
        : "+f"((C)[0]), "+f"((C)[1]), "+f"((C)[2]), "+f"((C)[3]) \
        : "r"((A)[0]), "r"((A)[1]), "r"((A)[2]), "r"((A)[3]), "r"(b0), "r"(b1))

__device__ __forceinline__ float warpReduce(float v) {
    #pragma unroll
    for (int o = 16; o > 0; o >>= 1) v += __shfl_xor_sync(0xffffffffu, v, o);
    return v;
}
__device__ __forceinline__ float dot4(float4 a, float4 b) {
    return a.x*b.x + a.y*b.y + a.z*b.z + a.w*b.w;
}

// ======================= kernel 0a: per-hop scalar constants + gw =======================
__global__ void const_kernel(const float* __restrict__ pos,
                             const float* __restrict__ gamma,
                             const float* __restrict__ beta,
                             const float* __restrict__ wp,
                             const float* __restrict__ bp) {
    const int bid = blockIdx.x;
    const int tid = threadIdx.x;
    __shared__ float red[3][8];
    const int lane = tid & 31, wid = tid >> 5;
    if (bid < NHOP) {
        float sp = 0.f, mp = 0.f, qp = 0.f;
        for (int h = tid; h < HH; h += 256) {
            float pv = pos[bid*HH + h];
            sp += pv * gamma[h] * wp[h];
            mp += pv;
            qp += pv * pv;
        }
        sp = warpReduce(sp); mp = warpReduce(mp); qp = warpReduce(qp);
        if (lane == 0) { red[0][wid] = sp; red[1][wid] = mp; red[2][wid] = qp; }
        __syncthreads();
        if (tid == 0) {
            float s = 0.f, m = 0.f, q = 0.f;
            #pragma unroll
            for (int i = 0; i < 8; i++) { s += red[0][i]; m += red[1][i]; q += red[2][i]; }
            g_spk[bid] = s;
            g_mupos[bid] = m * (1.f / HH);
            g_qpos[bid] = q * (1.f / HH);
        }
    } else {
        float c0 = 0.f, g = 0.f;
        for (int h = tid; h < HH; h += 256) {
            float gw = gamma[h] * wp[h];
            g_gw[h] = gw;
            c0 += beta[h] * wp[h];
            g  += gw;
        }
        c0 = warpReduce(c0); g = warpReduce(g);
        if (lane == 0) { red[0][wid] = c0; red[1][wid] = g; }
        __syncthreads();
        if (tid == 0) {
            float s = 0.f, s2 = 0.f;
            #pragma unroll
            for (int i = 0; i < 8; i++) { s += red[0][i]; s2 += red[1][i]; }
            g_C0 = s + bp[0];
            g_G = s2;
        }
    }
}

// ============ kernel 0b: build B_ext rows (fused c_k computation) ============
__global__ __launch_bounds__(256)
void splitB_kernel(const float* __restrict__ pos,
                   const float* __restrict__ Wt,
                   const float* __restrict__ bt) {
    const int o = blockIdx.x;
    const int tid = threadIdx.x;
    const int lane = tid & 31, wid = tid >> 5;
    __half* dst = g_Bsplit + (size_t)o * K2;

    float4 v = ((const float4*)(Wt + (size_t)o * HH))[tid];
    {
        __half hi[4];
        hi[0] = __float2half_rn(v.x);
        hi[1] = __float2half_rn(v.y);
        hi[2] = __float2half_rn(v.z);
        hi[3] = __float2half_rn(v.w);
        *(uint2*)(dst + 4*tid) = *(uint2*)hi;
    }

    const float4* p4 = (const float4*)pos;
    float acc[NHOP];
    #pragma unroll
    for (int k = 0; k < NHOP; k++)
        acc[k] = dot4(v, p4[k*(HH/4) + tid]);

    __shared__ float red[NHOP][8];
    __shared__ float c_s[NHOP];
    #pragma unroll
    for (int k = 0; k < NHOP; k++) {
        float r = warpReduce(acc[k]);
        if (lane == 0) red[k][wid] = r;
    }
    __syncthreads();
    if (tid < NHOP) {
        float s = 0.f;
        #pragma unroll
        for (int i = 0; i < 8; i++) s += red[tid][i];
        c_s[tid] = s + bt[o];
    }
    __syncthreads();

    if (tid < KEXT) {
        __half val = __float2half_rn(0.f);
        if (tid < 24) {
            int k = (tid < 12) ? tid : tid - 12;
            val = __float2half_rn(c_s[k]);
        } else if (tid < 36) {
            float c = c_s[tid-24];
            __half h = __float2half_rn(c);
            val = __float2half_rn(c - __half2float(h));
        }
        dst[KSPL + tid] = val;
    }
}

// ========= kernel 1: warp-per-token stats + ACT + scaled A write (2-pass, low regs) =========
__global__ __launch_bounds__(256)
void token_stats_kernel(const float* __restrict__ inp,
                        const float* __restrict__ tenc,
                        const float* __restrict__ pos,
                        float* __restrict__ out_rem,
                        float* __restrict__ out_nup) {
    const int warp = threadIdx.x >> 5;
    const int lane = threadIdx.x & 31;
    const int m = blockIdx.x * 8 + warp;

    const float4* in4 = (const float4*)inp + (size_t)m * (HH/4);
    const float4* t4p = (const float4*)tenc + (size_t)(m & (TT-1)) * (HH/4);
    const float4* gw4 = (const float4*)g_gw;
    const float4* p4  = (const float4*)pos;

    // pass 1: stats (no caching of base -> low register pressure)
    float s0 = 0.f, s1 = 0.f, s2 = 0.f;
    float sp[NHOP];
    #pragma unroll
    for (int k = 0; k < NHOP; k++) sp[k] = 0.f;
    #pragma unroll
    for (int seg = 0; seg < 8; seg++) {
        float4 a = in4[seg*32 + lane];
        float4 t = t4p[seg*32 + lane];
        float4 b = make_float4(a.x+t.x, a.y+t.y, a.z+t.z, a.w+t.w);
        s0 += b.x + b.y + b.z + b.w;
        s1 += dot4(b, b);
        s2 += dot4(b, gw4[seg*32 + lane]);
        #pragma unroll
        for (int k = 0; k < NHOP; k++)
            sp[k] += dot4(b, p4[k*(HH/4) + seg*32 + lane]);
    }

    s0 = warpReduce(s0); s1 = warpReduce(s1); s2 = warpReduce(s2);
    #pragma unroll
    for (int k = 0; k < NHOP; k++) sp[k] = warpReduce(sp[k]);

    const float mu_b = s0 * (1.f / HH);
    const float q_b  = s1 * (1.f / HH);
    const float G = g_G, C0 = g_C0;

    float hp = 0.f, rem = 0.f, nup = 0.f;
    float uw[NHOP];
    #pragma unroll
    for (int k = 0; k < NHOP; k++) {
        float mu  = mu_b + g_mupos[k];
        float ex2 = q_b + 2.f * sp[k] * (1.f / HH) + g_qpos[k];
        float var = ex2 - mu * mu;
        float Sg  = s2 + g_spk[k];
        float logit = rsqrtf(var + LNEPS) * (Sg - mu * G) + C0;
        float p = 1.f / (1.f + expf(-logit));

        float sr  = (hp < 1.f) ? 1.f : 0.f;
        float acc = hp + p * sr;
        float nh  = (acc > THRESH) ? sr : 0.f;
        sr        = (acc <= THRESH) ? sr : 0.f;
        hp  = hp + p * sr;
        rem = rem + nh * (1.f - hp);
        hp  = hp + nh * rem;
        nup = nup + sr + nh;
        uw[k] = p * sr + nh * rem;
    }
    float wv[NHOP];
    float prod = 1.f, Ac = 0.f;
    #pragma unroll
    for (int k = NHOP-1; k >= 0; k--) {
        float wk = uw[k] * prod;
        wv[k] = wk;
        Ac += wk;
        prod *= (1.f - uw[k]);
    }
    if (lane == 0) { out_rem[m] = rem; out_nup[m] = nup; }

    // pass 2: reload base (L1-resident) and write scaled hi-split A
    __half* dst = g_Asplit + (size_t)m * K2;
    #pragma unroll
    for (int seg = 0; seg < 8; seg++) {
        float4 a = in4[seg*32 + lane];
        float4 t = t4p[seg*32 + lane];
        __half hi[4];
        hi[0] = __float2half_rn(Ac*(a.x+t.x));
        hi[1] = __float2half_rn(Ac*(a.y+t.y));
        hi[2] = __float2half_rn(Ac*(a.z+t.z));
        hi[3] = __float2half_rn(Ac*(a.w+t.w));
        *(uint2*)(dst + seg*128 + lane*4) = *(uint2*)hi;
    }
    {
        __half v0 = __float2half_rn(0.f), v1 = __float2half_rn(0.f);
        int j = lane;
        if (j < 12) v0 = __float2half_rn(wv[j]);
        else if (j < 24) {
            float w = wv[j-12];
            __half h = __float2half_rn(w);
            v0 = __float2half_rn(w - __half2float(h));
        } else {
            v0 = __float2half_rn(wv[j-24]);
        }
        int j2 = lane + 32;
        if (j2 < 36) v1 = __float2half_rn(wv[j2-24]);
        dst[KSPL + j]  = v0;
        dst[KSPL + j2] = v1;
    }
}

// ======================= kernel 2: fp16 mma.sync GEMM (3-stage pipeline) =======================
// 128x128 CTA tile, 256 threads, warp grid 2(M) x 4(N), warp tile 64x32, 2 CTAs/SM.

#define TM 128
#define TN 128
#define ROWB 144                        // padded row bytes: 64 fp16 = 128B + 16B pad
#define ABYTES (TM * ROWB)              // 18432
#define BBYTES (TN * ROWB)              // 18432
#define STAGEB (ABYTES + BBYTES)        // 36864
#define NSTAGE 3
#define SMEM_GEMM (NSTAGE * STAGEB)     // 110592

__device__ __forceinline__ void load_tiles(uint32_t sa, int stage, int kt, int bm, int bn, int tid) {
    const __half* Ab = g_Asplit + (size_t)bm * K2 + kt * KT;
    uint32_t adst = sa + stage * STAGEB;
    #pragma unroll
    for (int i = 0; i < 4; i++) {
        int id = tid + i * 256;
        int row = id >> 3, cc = id & 7;
        cp16(adst + row * ROWB + cc * 16, Ab + (size_t)row * K2 + cc * 8);
    }
    const __half* Bb = g_Bsplit + (size_t)bn * K2 + kt * KT;
    uint32_t bdst = sa + stage * STAGEB + ABYTES;
    #pragma unroll
    for (int i = 0; i < 4; i++) {
        int id = tid + i * 256;
        int row = id >> 3, cc = id & 7;
        cp16(bdst + row * ROWB + cc * 16, Bb + (size_t)row * K2 + cc * 8);
    }
}

__global__ __launch_bounds__(256, 2)
void gemm_mma_kernel(float* __restrict__ outp) {
    extern __shared__ char smem[];
    uint32_t sa = smem_u32(smem);
    const int tid = threadIdx.x;
    const int lane = tid & 31;
    const int warp = tid >> 5;
    const int wm = (warp & 1) * 64;    // 2 warps along M (64 rows each)
    const int wn = (warp >> 1) * 32;   // 4 warps along N (32 cols each)
    const int bm = blockIdx.y * TM;
    const int bn = blockIdx.x * TN;

    const int g = lane >> 3, r = lane & 7;
    const uint32_t a_lm = sa + (uint32_t)((wm + (g & 1) * 8 + r) * ROWB + (g >> 1) * 16);
    const uint32_t b_lm = sa + ABYTES + (uint32_t)((wn + (g >> 1) * 8 + r) * ROWB + (g & 1) * 16);

    float acc[4][2][8];
    #pragma unroll
    for (int i = 0; i < 4; i++)
        #pragma unroll
        for (int j = 0; j < 2; j++)
            #pragma unroll
            for (int q = 0; q < 8; q++) acc[i][j][q] = 0.f;

    // prologue: 2 tiles in flight
    load_tiles(sa, 0, 0, bm, bn, tid);
    CP_COMMIT();
    load_tiles(sa, 1, 1, bm, bn, tid);
    CP_COMMIT();

    int stage = 0;
    for (int kt = 0; kt < NT; kt++) {
        asm volatile("cp.async.wait_group 1;" ::: "memory");   // load kt done
        __syncthreads();                                       // publish + overwrite-safety

        // issue next load ASAP (into the stage consumed at kt-1)
        if (kt + 2 < NT) {
            int nstage = stage + 2; if (nstage >= NSTAGE) nstage -= NSTAGE;
            load_tiles(sa, nstage, kt + 2, bm, bn, tid);
        }
        CP_COMMIT();   // uniform group accounting (possibly empty)

        const uint32_t abuf = a_lm + stage * STAGEB;
        const uint32_t bbuf = b_lm + stage * STAGEB;

        #pragma unroll
        for (int ks = 0; ks < 4; ks++) {
            uint32_t af[4][4];
            #pragma unroll
            for (int mf = 0; mf < 4; mf++)
                LDSM4(af[mf], abuf + mf * (16 * ROWB) + ks * 32);
            uint32_t bfr[2][4];
            #pragma unroll
            for (int nf = 0; nf < 2; nf++)
                LDSM4(bfr[nf], bbuf + nf * (16 * ROWB) + ks * 32);
            #pragma unroll
            for (int mf = 0; mf < 4; mf++)
                #pragma unroll
                for (int nf = 0; nf < 2; nf++) {
                    MMA16816(acc[mf][nf] + 0, af[mf], bfr[nf][0], bfr[nf][1]);
                    MMA16816(acc[mf][nf] + 4, af[mf], bfr[nf][2], bfr[nf][3]);
                }
        }
        stage++; if (stage >= NSTAGE) stage = 0;
    }

    // store
    #pragma unroll
    for (int mf = 0; mf < 4; mf++) {
        #pragma unroll
        for (int nf = 0; nf < 2; nf++) {
            const int row0 = bm + wm + mf * 16 + (lane >> 2);
            const int col0 = bn + wn + nf * 16 + (lane & 3) * 2;
            float* p = outp + (size_t)row0 * HH + col0;
            *(float2*)(p)              = make_float2(acc[mf][nf][0], acc[mf][nf][1]);
            *(float2*)(p + 8*HH)       = make_float2(acc[mf][nf][2], acc[mf][nf][3]);
            *(float2*)(p + 8)          = make_float2(acc[mf][nf][4], acc[mf][nf][5]);
            *(float2*)(p + 8*HH + 8)   = make_float2(acc[mf][nf][6], acc[mf][nf][7]);
        }
    }
}

// ======================= host launch =======================
extern "C" void kernel_launch(void* const* d_in, const int* in_sizes, int n_in,
                              void* d_out, int out_size) {
    const float* inp   = (const float*)d_in[0];
    const float* tenc  = (const float*)d_in[1];
    const float* pos   = (const float*)d_in[2];
    const float* gamma = (const float*)d_in[3];
    const float* beta  = (const float*)d_in[4];
    const float* wp    = (const float*)d_in[5];
    const float* bp    = (const float*)d_in[6];
    const float* Wt    = (const float*)d_in[7];
    const float* bt    = (const float*)d_in[8];

    float* outp    = (float*)d_out;
    float* out_rem = outp + (size_t)MM * HH;
    float* out_nup = out_rem + MM;

    cudaFuncSetAttribute(gemm_mma_kernel, cudaFuncAttributeMaxDynamicSharedMemorySize, SMEM_GEMM);

    const_kernel<<<NHOP + 1, 256>>>(pos, gamma, beta, wp, bp);
    splitB_kernel<<<HH, 256>>>(pos, Wt, bt);
    token_stats_kernel<<<MM / 8, 256>>>(inp, tenc, pos, out_rem, out_nup);
    gemm_mma_kernel<<<dim3(HH / TN, MM / TM), 256, SMEM_GEMM>>>(outp);
}